// round 9
// baseline (speedup 1.0000x reference)
#include <cuda_runtime.h>
#include <cuda_bf16.h>
#include <math.h>
#include <stdint.h>

#define B_    16
#define T_    400
#define DV_   4096
#define DS_   768
#define D_    1024
#define L_    32
#define NSEG  16
#define FPS_  25
#define NPROP 136

// ---------------- scratch (static device globals; no allocation) ----------------
__device__ float    g_Vr[B_ * T_ * D_];          // 26.2 MB
__device__ float    g_Sr[B_ * L_ * D_];          // 2.1 MB
__device__ float    g_scores[B_ * L_ * T_];
__device__ float    g_wtil[B_ * L_ * T_];
__device__ float    g_m[B_ * L_ * NSEG];
__device__ float    g_Zs[B_ * L_ * NSEG];
__device__ float    g_E[B_ * L_ * NSEG * D_];    // 33.5 MB
__device__ float    g_snorm[B_ * D_];
__device__ unsigned g_negmax[B_];

// split-bf16 operands for the big GEMM
__device__ __align__(16) __nv_bfloat16 g_Ahi[(long)B_ * T_ * DV_];  // [M,K] 52.4 MB
__device__ __align__(16) __nv_bfloat16 g_Alo[(long)B_ * T_ * DV_];
__device__ __align__(16) __nv_bfloat16 g_Bhi[(long)D_ * DV_];       // [N,K]
__device__ __align__(16) __nv_bfloat16 g_Blo[(long)D_ * DV_];

// ---------------- helpers ----------------
__device__ __forceinline__ uint32_t smem_u32(const void* p) {
    uint32_t a;
    asm("{ .reg .u64 t; cvta.to.shared.u64 t, %1; cvt.u32.u64 %0, t; }" : "=r"(a) : "l"(p));
    return a;
}
#define CP_ASYNC16(dst, src) \
    asm volatile("cp.async.cg.shared.global [%0], [%1], 16;" :: "r"(dst), "l"(src) : "memory")
#define CP_COMMIT() asm volatile("cp.async.commit_group;" ::: "memory")
#define CP_WAIT(n)  asm volatile("cp.async.wait_group %0;" :: "n"(n) : "memory")

__device__ __forceinline__ void mma16816(float* c, const uint32_t* a, const uint32_t* b) {
    asm volatile(
        "mma.sync.aligned.m16n8k16.row.col.f32.bf16.bf16.f32 "
        "{%0,%1,%2,%3}, {%4,%5,%6,%7}, {%8,%9}, {%0,%1,%2,%3};"
        : "+f"(c[0]), "+f"(c[1]), "+f"(c[2]), "+f"(c[3])
        : "r"(a[0]), "r"(a[1]), "r"(a[2]), "r"(a[3]), "r"(b[0]), "r"(b[1]));
}

__device__ __forceinline__ void ldsm_x4(uint32_t& r0, uint32_t& r1, uint32_t& r2,
                                        uint32_t& r3, uint32_t addr) {
    asm volatile("ldmatrix.sync.aligned.m8n8.x4.shared.b16 {%0,%1,%2,%3}, [%4];"
                 : "=r"(r0), "=r"(r1), "=r"(r2), "=r"(r3) : "r"(addr));
}

// ============================================================================
// Vr GEMM v5: C = A(split bf16)[M,K] @ B(split bf16)[N,K]^T + bias
// 128x128 tile, BK=32, 2-stage cp.async, ldmatrix, term-pass mma, 2 CTAs/SM.
// Pure LDSM+HMMA mainloop (A pre-split in global memory).
// ============================================================================
#define BK      32
#define B_LDT   40                          // bf16 per smem row (32 + 8 pad)
#define B_ROWB  (B_LDT * 2)                 // 80 bytes per row
#define TILE_B  (128 * B_ROWB)              // 10240 bytes per matrix tile
#define STAGE_B (4 * TILE_B)                // 40960: Ah, Al, Bh, Bl
#define GEMM_SMEM (2 * STAGE_B)             // 81920

__device__ __forceinline__ void load_stage(
    uint32_t sbase,
    const __nv_bfloat16* __restrict__ Ah, const __nv_bfloat16* __restrict__ Al,
    const __nv_bfloat16* __restrict__ Bh, const __nv_bfloat16* __restrict__ Bl,
    int m0, int n0, int k0, int tid)
{
#pragma unroll
    for (int i = 0; i < 8; i++) {
        int c = i * 256 + tid;
        int mat = c >> 9;              // 0:Ah 1:Al 2:Bh 3:Bl
        int rem = c & 511;
        int row = rem >> 2;
        int ch  = rem & 3;
        const __nv_bfloat16* gp;
        long roff;
        if (mat == 0)      { gp = Ah; roff = (long)(m0 + row) * DV_; }
        else if (mat == 1) { gp = Al; roff = (long)(m0 + row) * DV_; }
        else if (mat == 2) { gp = Bh; roff = (long)(n0 + row) * DV_; }
        else               { gp = Bl; roff = (long)(n0 + row) * DV_; }
        roff += k0 + ch * 8;
        uint32_t dst = sbase + mat * TILE_B + row * B_ROWB + ch * 16;
        CP_ASYNC16(dst, gp + roff);
    }
}

__global__ void __launch_bounds__(256, 2) vr_gemm(
    const __nv_bfloat16* __restrict__ Ah, const __nv_bfloat16* __restrict__ Al,
    const __nv_bfloat16* __restrict__ Bh, const __nv_bfloat16* __restrict__ Bl,
    const float* __restrict__ bias, float* __restrict__ C)
{
    extern __shared__ char smc[];
    uint32_t sb = smem_u32(smc);
    int tid = threadIdx.x, wid = tid >> 5, lane = tid & 31;
    int g = lane >> 2, tig = lane & 3;
    int wm = wid >> 2, wn = wid & 3;          // 2 x 4 warp grid
    int n0 = blockIdx.x * 128, m0 = blockIdx.y * 128;

    float acc[4][4][4];
#pragma unroll
    for (int a = 0; a < 4; a++)
#pragma unroll
        for (int b = 0; b < 4; b++)
#pragma unroll
            for (int cc = 0; cc < 4; cc++) acc[a][b][cc] = 0.f;

    // ldmatrix per-thread base offsets
    uint32_t aRowOff = (uint32_t)(wm * 64 + (lane & 15)) * B_ROWB + (lane >> 4) * 16;
    uint32_t bRowOff = (uint32_t)(wn * 32 + (lane >> 4) * 8 + (lane & 7)) * B_ROWB
                       + ((lane >> 3) & 1) * 16;

    load_stage(sb, Ah, Al, Bh, Bl, m0, n0, 0, tid);
    CP_COMMIT();

    const int NKT = DV_ / BK;   // 128
    for (int kt = 0; kt < NKT; kt++) {
        if (kt + 1 < NKT) {
            load_stage(sb + ((kt + 1) & 1) * STAGE_B, Ah, Al, Bh, Bl,
                       m0, n0, (kt + 1) * BK, tid);
            CP_COMMIT();
            CP_WAIT(1);
        } else {
            CP_WAIT(0);
        }
        __syncthreads();

        uint32_t stg = sb + (kt & 1) * STAGE_B;
        uint32_t aH = stg + aRowOff;
        uint32_t aL = stg + TILE_B + aRowOff;
        uint32_t bH = stg + 2 * TILE_B + bRowOff;
        uint32_t bL = stg + 3 * TILE_B + bRowOff;

#pragma unroll
        for (int ks = 0; ks < 2; ks++) {
            uint32_t kso = ks * 32;           // 16 bf16 = 32B per k-chunk
            uint32_t bh[4][2], bl[4][2];
            ldsm_x4(bh[0][0], bh[0][1], bh[1][0], bh[1][1], bH + kso);
            ldsm_x4(bh[2][0], bh[2][1], bh[3][0], bh[3][1], bH + 16 * B_ROWB + kso);
            ldsm_x4(bl[0][0], bl[0][1], bl[1][0], bl[1][1], bL + kso);
            ldsm_x4(bl[2][0], bl[2][1], bl[3][0], bl[3][1], bL + 16 * B_ROWB + kso);
#pragma unroll
            for (int mi = 0; mi < 4; mi++) {
                uint32_t ah[4], al[4];
                ldsm_x4(ah[0], ah[1], ah[2], ah[3], aH + mi * 16 * B_ROWB + kso);
                ldsm_x4(al[0], al[1], al[2], al[3], aL + mi * 16 * B_ROWB + kso);
#pragma unroll
                for (int ni = 0; ni < 4; ni++) mma16816(acc[mi][ni], ah, bh[ni]);
#pragma unroll
                for (int ni = 0; ni < 4; ni++) mma16816(acc[mi][ni], ah, bl[ni]);
#pragma unroll
                for (int ni = 0; ni < 4; ni++) mma16816(acc[mi][ni], al, bh[ni]);
            }
        }
        __syncthreads();
    }

    // epilogue: C[m, n] = acc + bias[n]
#pragma unroll
    for (int mi = 0; mi < 4; mi++) {
        int mA = m0 + wm * 64 + mi * 16 + g;
#pragma unroll
        for (int ni = 0; ni < 4; ni++) {
            int n = n0 + wn * 32 + ni * 8 + tig * 2;
            float b0 = bias[n], b1 = bias[n + 1];
            float2 v0 = make_float2(acc[mi][ni][0] + b0, acc[mi][ni][1] + b1);
            float2 v1 = make_float2(acc[mi][ni][2] + b0, acc[mi][ni][3] + b1);
            *(float2*)&C[(long)mA * D_ + n] = v0;
            *(float2*)&C[(long)(mA + 8) * D_ + n] = v1;
        }
    }
}

// ---------------- split fp32 -> (hi, lo) bf16 ----------------
__global__ void splitA_kernel(const float* __restrict__ A,
                              __nv_bfloat16* __restrict__ hi, __nv_bfloat16* __restrict__ lo)
{
    long i = ((long)blockIdx.x * 256 + threadIdx.x) * 4;
    float4 v = *(const float4*)(A + i);
    float x[4] = {v.x, v.y, v.z, v.w};
    __nv_bfloat16 h[4], l[4];
#pragma unroll
    for (int j = 0; j < 4; j++) {
        h[j] = __float2bfloat16(x[j]);
        l[j] = __float2bfloat16(x[j] - __bfloat162float(h[j]));
    }
    __nv_bfloat162 h01; h01.x = h[0]; h01.y = h[1];
    __nv_bfloat162 h23; h23.x = h[2]; h23.y = h[3];
    __nv_bfloat162 l01; l01.x = l[0]; l01.y = l[1];
    __nv_bfloat162 l23; l23.x = l[2]; l23.y = l[3];
    *(__nv_bfloat162*)(hi + i) = h01;
    *(__nv_bfloat162*)(hi + i + 2) = h23;
    *(__nv_bfloat162*)(lo + i) = l01;
    *(__nv_bfloat162*)(lo + i + 2) = l23;
}

// W [K=4096, N=1024] fp32 -> transposed split bf16 [N, K]
__global__ void splitW_kernel(const float* __restrict__ W,
                              __nv_bfloat16* __restrict__ hi, __nv_bfloat16* __restrict__ lo)
{
    __shared__ float t[32][33];
    int k0 = blockIdx.x * 32, n0 = blockIdx.y * 32;
    int tx = threadIdx.x, ty = threadIdx.y;
#pragma unroll
    for (int i = 0; i < 32; i += 8)
        t[ty + i][tx] = W[(long)(k0 + ty + i) * D_ + n0 + tx];
    __syncthreads();
#pragma unroll
    for (int i = 0; i < 32; i += 8) {
        int n = n0 + ty + i, k = k0 + tx;
        float x = t[tx][ty + i];
        __nv_bfloat16 h = __float2bfloat16(x);
        hi[(long)n * DV_ + k] = h;
        lo[(long)n * DV_ + k] = __float2bfloat16(x - __bfloat162float(h));
    }
}

// ---------------- fp32 SGEMM 64x64 tiles (for Sr) ----------------
__global__ void sgemm64_bias(const float* __restrict__ A, const float* __restrict__ Bm,
                             const float* __restrict__ bias, float* __restrict__ C,
                             int M, int N, int K)
{
    const int BKs = 16;
    __shared__ float As[BKs][68];
    __shared__ float Bs[BKs][68];

    int tid = threadIdx.x;
    int m0 = blockIdx.y * 64, n0 = blockIdx.x * 64;
    int ty = tid >> 4, tx = tid & 15;

    float acc[4][4];
#pragma unroll
    for (int i = 0; i < 4; i++)
#pragma unroll
        for (int j = 0; j < 4; j++) acc[i][j] = 0.f;

    int arow = tid >> 2, acol = (tid & 3) * 4;
    int brow = tid >> 4, bcol = (tid & 15) * 4;

    for (int k0 = 0; k0 < K; k0 += BKs) {
        {
            float4 v = *(const float4*)&A[(long)(m0 + arow) * K + k0 + acol];
            As[acol + 0][arow] = v.x; As[acol + 1][arow] = v.y;
            As[acol + 2][arow] = v.z; As[acol + 3][arow] = v.w;
        }
        {
            float4 v = *(const float4*)&Bm[(long)(k0 + brow) * N + n0 + bcol];
            Bs[brow][bcol + 0] = v.x; Bs[brow][bcol + 1] = v.y;
            Bs[brow][bcol + 2] = v.z; Bs[brow][bcol + 3] = v.w;
        }
        __syncthreads();
#pragma unroll
        for (int kk = 0; kk < BKs; kk++) {
            float4 a = *(const float4*)&As[kk][ty * 4];
            float4 b = *(const float4*)&Bs[kk][tx * 4];
            float av[4] = {a.x, a.y, a.z, a.w};
            float bv[4] = {b.x, b.y, b.z, b.w};
#pragma unroll
            for (int i = 0; i < 4; i++)
#pragma unroll
                for (int j = 0; j < 4; j++) acc[i][j] += av[i] * bv[j];
        }
        __syncthreads();
    }

    float4 bb = *(const float4*)&bias[n0 + tx * 4];
    float bvv[4] = {bb.x, bb.y, bb.z, bb.w};
#pragma unroll
    for (int i = 0; i < 4; i++) {
        float4 o;
        o.x = acc[i][0] + bvv[0]; o.y = acc[i][1] + bvv[1];
        o.z = acc[i][2] + bvv[2]; o.w = acc[i][3] + bvv[3];
        *(float4*)&C[(long)(m0 + ty * 4 + i) * N + n0 + tx * 4] = o;
    }
}

// ---------------- Sr column norms ----------------
__global__ void snorm_kernel()
{
    int id = blockIdx.x * 256 + threadIdx.x;
    int b = id >> 10, d = id & 1023;
    float s = 0.f;
#pragma unroll
    for (int l = 0; l < L_; l++) {
        float v = g_Sr[(b * L_ + l) * D_ + d];
        s += v * v;
    }
    g_snorm[id] = sqrtf(s);
}

// ---------------- scores[b,l,t] = Sr[b,l,:]·Vr[b,t,:] ----------------
__global__ void scores_kernel()
{
    int b = blockIdx.y;
    int t0 = blockIdx.x * 64;
    __shared__ float sS[32][36];
    __shared__ float sV[32][68];
    int tid = threadIdx.x;
    int ty = tid >> 4, tx = tid & 15;
    float acc[2][4] = {{0, 0, 0, 0}, {0, 0, 0, 0}};

    int lrow = tid >> 3, kc = (tid & 7) * 4;
    for (int k0 = 0; k0 < D_; k0 += 32) {
        {
            float4 v = *(const float4*)&g_Sr[(b * L_ + lrow) * D_ + k0 + kc];
            sS[kc + 0][lrow] = v.x; sS[kc + 1][lrow] = v.y;
            sS[kc + 2][lrow] = v.z; sS[kc + 3][lrow] = v.w;
        }
#pragma unroll
        for (int i = 0; i < 2; i++) {
            int tt = lrow + i * 32;
            int t = t0 + tt;
            float4 w = make_float4(0.f, 0.f, 0.f, 0.f);
            if (t < T_) w = *(const float4*)&g_Vr[((long)b * T_ + t) * D_ + k0 + kc];
            sV[kc + 0][tt] = w.x; sV[kc + 1][tt] = w.y;
            sV[kc + 2][tt] = w.z; sV[kc + 3][tt] = w.w;
        }
        __syncthreads();
#pragma unroll
        for (int kk = 0; kk < 32; kk++) {
            float a0 = sS[kk][ty * 2], a1 = sS[kk][ty * 2 + 1];
            float4 bv = *(const float4*)&sV[kk][tx * 4];
            acc[0][0] += a0 * bv.x; acc[0][1] += a0 * bv.y;
            acc[0][2] += a0 * bv.z; acc[0][3] += a0 * bv.w;
            acc[1][0] += a1 * bv.x; acc[1][1] += a1 * bv.y;
            acc[1][2] += a1 * bv.z; acc[1][3] += a1 * bv.w;
        }
        __syncthreads();
    }
#pragma unroll
    for (int i = 0; i < 2; i++) {
        int l = ty * 2 + i;
#pragma unroll
        for (int j = 0; j < 4; j++) {
            int t = t0 + tx * 4 + j;
            if (t < T_) g_scores[(b * L_ + l) * T_ + t] = acc[i][j];
        }
    }
}

// ---------------- per-segment max/Z + exp weights ----------------
__global__ void segprep_kernel()
{
    int bl = blockIdx.x;
    __shared__ float sm[NSEG];
    int tid = threadIdx.x;
    const float* row = g_scores + bl * T_;
    if (tid < NSEG) {
        float mx = -INFINITY;
#pragma unroll
        for (int i = 0; i < FPS_; i++) mx = fmaxf(mx, row[tid * FPS_ + i]);
        float z = 0.f;
#pragma unroll
        for (int i = 0; i < FPS_; i++) z += expf(row[tid * FPS_ + i] - mx);
        sm[tid] = mx;
        g_m[bl * NSEG + tid] = mx;
        g_Zs[bl * NSEG + tid] = z;
    }
    __syncthreads();
    for (int t = tid; t < T_; t += 256)
        g_wtil[bl * T_ + t] = expf(row[t] - sm[t / FPS_]);
}

// ---------------- E[b,l,g,d] = sum_{t in seg g} wtil * Vr[b,t,d] ----------------
__global__ void eagg_kernel()
{
    int dc = blockIdx.x, g = blockIdx.y, b = blockIdx.z;
    int tid = threadIdx.x;
    int d = dc * 256 + tid;
    __shared__ float Vs[FPS_][256];
    __shared__ float ws[L_][FPS_ + 1];
#pragma unroll
    for (int t = 0; t < FPS_; t++)
        Vs[t][tid] = g_Vr[((long)b * T_ + g * FPS_ + t) * D_ + d];
    for (int i = tid; i < L_ * FPS_; i += 256) {
        int l = i / FPS_, t = i % FPS_;
        ws[l][t] = g_wtil[(b * L_ + l) * T_ + g * FPS_ + t];
    }
    __syncthreads();
    for (int l = 0; l < L_; l++) {
        float acc = 0.f;
#pragma unroll
        for (int t = 0; t < FPS_; t++) acc += ws[l][t] * Vs[t][tid];
        g_E[((long)(b * L_ + l) * NSEG + g) * D_ + d] = acc;
    }
}

// ============================================================================
// prop_kernel v3: barrier-free chain streaming.
// ============================================================================
#define PCH 128
__global__ void __launch_bounds__(PCH) prop_kernel(const int* __restrict__ ytrue,
                                                   float* __restrict__ outPos)
{
    int b = blockIdx.y, dc = blockIdx.x, sg = blockIdx.z;
    int tid = threadIdx.x;
    int d = dc * PCH + tid;

    __shared__ float s_m[L_][NSEG], s_Z[L_][NSEG];
    __shared__ float sSr[L_][PCH];
    __shared__ float c_sc[40][L_], c_an[40][L_], c_iz[40][L_];

    for (int i = tid; i < L_ * NSEG; i += PCH) {
        int l = i >> 4, g = i & 15;
        s_m[l][g] = g_m[(b * L_ + l) * NSEG + g];
        s_Z[l][g] = g_Zs[(b * L_ + l) * NSEG + g];
    }
    for (int i = tid; i < L_ * PCH; i += PCH) {
        int l = i / PCH, j = i % PCH;
        sSr[l][j] = g_Sr[(b * L_ + l) * D_ + dc * PCH + j];
    }
    __syncthreads();

    {
        int l = tid & 31, ci = tid >> 5;
        int s = sg + 4 * ci;
        int base = 0;
#pragma unroll
        for (int j = 0; j < 4; j++) if (j < ci) base += NSEG - (sg + 4 * j);
        float M = s_m[l][s], Zw = s_Z[l][s];
        c_sc[base][l] = 0.f; c_an[base][l] = 1.f; c_iz[base][l] = 1.f / Zw;
        for (int e = s + 1; e < NSEG; e++) {
            float mv = s_m[l][e];
            float Mn = fmaxf(M, mv);
            float sc = expf(M - Mn), an = expf(mv - Mn);
            Zw = Zw * sc + an * s_Z[l][e];
            M = Mn;
            int st = base + e - s;
            c_sc[st][l] = sc; c_an[st][l] = an; c_iz[st][l] = 1.f / Zw;
        }
    }
    __syncthreads();

    float sn = g_snorm[b * D_ + d];
    int ys = ytrue[2 * b], ye = ytrue[2 * b + 1];
    float negmax = -INFINITY;

    int base = 0;
#pragma unroll 1
    for (int ci = 0; ci < 4; ci++) {
        int s = sg + 4 * ci;
        float U[L_];
#pragma unroll
        for (int l = 0; l < L_; l++) U[l] = 0.f;
#pragma unroll 1
        for (int e = s; e < NSEG; e++) {
            int st = base + e - s;
            float num = 0.f, sq = 0.f;
            const float* Eb = g_E + ((long)(b * L_) * NSEG + e) * D_ + d;
#pragma unroll
            for (int l = 0; l < L_; l++) {
                float Ev = Eb[(long)l * NSEG * D_];
                float u = U[l] * c_sc[st][l] + c_an[st][l] * Ev;
                U[l] = u;
                float o = u * c_iz[st][l];
                num += o * sSr[l][tid];
                sq += o * o;
            }
            float scv = num / (sqrtf(sq) * sn + 1e-15f);
            if (s == ys && e == ye) outPos[b * D_ + d] = scv;
            else negmax = fmaxf(negmax, scv);
        }
        base += NSEG - s;
    }

#pragma unroll
    for (int off = 16; off; off >>= 1)
        negmax = fmaxf(negmax, __shfl_xor_sync(0xffffffffu, negmax, off));
    __shared__ float wm[4];
    if ((tid & 31) == 0) wm[tid >> 5] = negmax;
    __syncthreads();
    if (tid == 0) {
        float v = fmaxf(fmaxf(wm[0], wm[1]), fmaxf(wm[2], wm[3]));
        unsigned u = __float_as_uint(v);
        u = (u & 0x80000000u) ? ~u : (u | 0x80000000u);
        atomicMax(&g_negmax[b], u);
    }
}

__global__ void init_neg()
{
    if (threadIdx.x < B_) g_negmax[threadIdx.x] = 0x007FFFFFu;
}

__global__ void fin_kernel(float* __restrict__ outNeg)
{
    int b = threadIdx.x;
    if (b < B_) {
        unsigned u = g_negmax[b];
        unsigned bits = (u & 0x80000000u) ? (u ^ 0x80000000u) : ~u;
        outNeg[b] = __uint_as_float(bits);
    }
}

// ---------------- launch ----------------
extern "C" void kernel_launch(void* const* d_in, const int* in_sizes, int n_in,
                              void* d_out, int out_size)
{
    const float* videos    = (const float*)d_in[0];
    const float* sentences = (const float*)d_in[1];
    const float* Wv        = (const float*)d_in[2];
    const float* bv        = (const float*)d_in[3];
    const float* Ws        = (const float*)d_in[4];
    const float* bs        = (const float*)d_in[5];
    const int*   ytrue     = (const int*)d_in[6];
    float* out = (float*)d_out;

    float *pVr = nullptr, *pSr = nullptr;
    void *pAhi = nullptr, *pAlo = nullptr, *pBhi = nullptr, *pBlo = nullptr;
    cudaGetSymbolAddress((void**)&pVr, g_Vr);
    cudaGetSymbolAddress((void**)&pSr, g_Sr);
    cudaGetSymbolAddress(&pAhi, g_Ahi);
    cudaGetSymbolAddress(&pAlo, g_Alo);
    cudaGetSymbolAddress(&pBhi, g_Bhi);
    cudaGetSymbolAddress(&pBlo, g_Blo);

    cudaFuncSetAttribute(vr_gemm, cudaFuncAttributeMaxDynamicSharedMemorySize, GEMM_SMEM);

    init_neg<<<1, 32>>>();                                              // 1
    splitA_kernel<<<(int)(((long)B_ * T_ * DV_) / (256 * 4)), 256>>>(   // 2
        videos, (__nv_bfloat16*)pAhi, (__nv_bfloat16*)pAlo);
    splitW_kernel<<<dim3(DV_ / 32, D_ / 32), dim3(32, 8)>>>(Wv,         // 3
        (__nv_bfloat16*)pBhi, (__nv_bfloat16*)pBlo);
    vr_gemm<<<dim3(D_ / 128, (B_ * T_) / 128), 256, GEMM_SMEM>>>(       // 4 (profiled)
        (const __nv_bfloat16*)pAhi, (const __nv_bfloat16*)pAlo,
        (const __nv_bfloat16*)pBhi, (const __nv_bfloat16*)pBlo, bv, pVr);
    sgemm64_bias<<<dim3(D_ / 64, (B_ * L_) / 64), 256>>>(sentences,     // 5
        Ws, bs, pSr, B_ * L_, D_, DS_);

    snorm_kernel<<<(B_ * D_) / 256, 256>>>();
    scores_kernel<<<dim3((T_ + 63) / 64, B_), 256>>>();
    segprep_kernel<<<B_ * L_, 256>>>();
    eagg_kernel<<<dim3(D_ / 256, NSEG, B_), 256>>>();
    prop_kernel<<<dim3(D_ / PCH, B_, 4), PCH>>>(ytrue, out);
    fin_kernel<<<1, 32>>>(out + B_ * D_);
}

// round 10
// speedup vs baseline: 1.1661x; 1.1661x over previous
#include <cuda_runtime.h>
#include <cuda_bf16.h>
#include <math.h>
#include <stdint.h>

#define B_    16
#define T_    400
#define DV_   4096
#define DS_   768
#define D_    1024
#define L_    32
#define NSEG  16
#define FPS_  25
#define NPROP 136

// ---------------- scratch (static device globals; no allocation) ----------------
__device__ float    g_Vr[B_ * T_ * D_];          // 26.2 MB
__device__ float    g_Sr[B_ * L_ * D_];          // 2.1 MB
__device__ float    g_scores[B_ * L_ * T_];
__device__ float    g_wtil[B_ * L_ * T_];
__device__ float    g_m[B_ * L_ * NSEG];
__device__ float    g_Zs[B_ * L_ * NSEG];
__device__ float    g_E[B_ * L_ * NSEG * D_];    // 33.5 MB
__device__ float    g_snorm[B_ * D_];
__device__ unsigned g_negmax[B_];

// split-bf16 W for the big GEMM (A split fused into the GEMM)
__device__ __align__(16) __nv_bfloat16 g_Bhi[(long)D_ * DV_];       // [N,K]
__device__ __align__(16) __nv_bfloat16 g_Blo[(long)D_ * DV_];

// ---------------- helpers ----------------
__device__ __forceinline__ uint32_t smem_u32(const void* p) {
    uint32_t a;
    asm("{ .reg .u64 t; cvta.to.shared.u64 t, %1; cvt.u32.u64 %0, t; }" : "=r"(a) : "l"(p));
    return a;
}
#define CP_ASYNC16(dst, src) \
    asm volatile("cp.async.cg.shared.global [%0], [%1], 16;" :: "r"(dst), "l"(src) : "memory")
#define CP_COMMIT() asm volatile("cp.async.commit_group;" ::: "memory")
#define CP_WAIT(n)  asm volatile("cp.async.wait_group %0;" :: "n"(n) : "memory")

__device__ __forceinline__ void mma16816(float* c, const uint32_t* a, const uint32_t* b) {
    asm volatile(
        "mma.sync.aligned.m16n8k16.row.col.f32.bf16.bf16.f32 "
        "{%0,%1,%2,%3}, {%4,%5,%6,%7}, {%8,%9}, {%0,%1,%2,%3};"
        : "+f"(c[0]), "+f"(c[1]), "+f"(c[2]), "+f"(c[3])
        : "r"(a[0]), "r"(a[1]), "r"(a[2]), "r"(a[3]), "r"(b[0]), "r"(b[1]));
}

__device__ __forceinline__ void ldsm_x4(uint32_t& r0, uint32_t& r1, uint32_t& r2,
                                        uint32_t& r3, uint32_t addr) {
    asm volatile("ldmatrix.sync.aligned.m8n8.x4.shared.b16 {%0,%1,%2,%3}, [%4];"
                 : "=r"(r0), "=r"(r1), "=r"(r2), "=r"(r3) : "r"(addr));
}

// split a float2 into packed bf16x2 (hi) and packed bf16x2 (residual lo)
__device__ __forceinline__ void splitpair(float2 v, uint32_t& h, uint32_t& l) {
    __nv_bfloat162 hb = __floats2bfloat162_rn(v.x, v.y);
    float2 hf = __bfloat1622float2(hb);
    __nv_bfloat162 lb = __floats2bfloat162_rn(v.x - hf.x, v.y - hf.y);
    h = *(uint32_t*)&hb;
    l = *(uint32_t*)&lb;
}

// ============================================================================
// Vr GEMM v6: C = A_fp32 @ B(split bf16)^T + bias
// 128x256 tile, BK=32, 2-stage cp.async; A split staged in smem once per tile;
// ldmatrix; term-pass mma. Convert cost amortized over 192 HMMA/kt.
// ============================================================================
#define BK      32
#define A_LDF   36                          // fp32 per A smem row (32 + 4 pad)
#define A_TB    (128 * A_LDF * 4)           // 18432 bytes (fp32 A stage)
#define B_LDT   40                          // bf16 per smem row (32 + 8 pad)
#define B_ROWB  (B_LDT * 2)                 // 80 bytes per row
#define BT_TB   (256 * B_ROWB)              // 20480 per B matrix tile (256 rows)
#define AH_TB   (128 * B_ROWB)              // 10240 converted-A buffer
#define STAGE_B (A_TB + 2 * BT_TB)          // 59392
#define AH_OFF  (2 * STAGE_B)               // 118784
#define AL_OFF  (AH_OFF + AH_TB)            // 129024
#define GEMM_SMEM (AL_OFF + AH_TB)          // 139264

__device__ __forceinline__ void load_stage(
    uint32_t sbase, const float* __restrict__ Af,
    const __nv_bfloat16* __restrict__ Bh, const __nv_bfloat16* __restrict__ Bl,
    int m0, int n0, int k0, int tid)
{
    // A fp32: 128 rows x 8 chunks
#pragma unroll
    for (int i = 0; i < 4; i++) {
        int c = i * 256 + tid;
        int row = c >> 3, ch = c & 7;
        CP_ASYNC16(sbase + row * (A_LDF * 4) + ch * 16,
                   Af + (long)(m0 + row) * DV_ + k0 + ch * 4);
    }
    // B hi/lo bf16: 256 rows x 4 chunks each
#pragma unroll
    for (int i = 0; i < 4; i++) {
        int c = i * 256 + tid;
        int row = c >> 2, ch = c & 3;
        long roff = (long)(n0 + row) * DV_ + k0 + ch * 8;
        uint32_t dd = row * B_ROWB + ch * 16;
        CP_ASYNC16(sbase + A_TB + dd, Bh + roff);
        CP_ASYNC16(sbase + A_TB + BT_TB + dd, Bl + roff);
    }
}

__global__ void __launch_bounds__(256) vr_gemm(
    const float* __restrict__ Af,
    const __nv_bfloat16* __restrict__ Bh, const __nv_bfloat16* __restrict__ Bl,
    const float* __restrict__ bias, float* __restrict__ C)
{
    extern __shared__ char smc[];
    uint32_t sb = smem_u32(smc);
    int tid = threadIdx.x, wid = tid >> 5, lane = tid & 31;
    int g = lane >> 2, tig = lane & 3;
    int wm = wid >> 2, wn = wid & 3;          // 2 x 4 warp grid (64 rows x 64 cols each)
    int n0 = blockIdx.x * 256, m0 = blockIdx.y * 128;

    float acc[4][8][4];
#pragma unroll
    for (int a = 0; a < 4; a++)
#pragma unroll
        for (int b = 0; b < 8; b++)
#pragma unroll
            for (int cc = 0; cc < 4; cc++) acc[a][b][cc] = 0.f;

    // conversion-phase indices
    int crow = tid >> 1, ccol = (tid & 1) * 16;

    // ldmatrix per-thread base offsets
    uint32_t aRowOff = (uint32_t)(wm * 64 + (lane & 15)) * B_ROWB + (lane >> 4) * 16;
    uint32_t bRowOff = (uint32_t)(wn * 64 + (lane >> 4) * 8 + (lane & 7)) * B_ROWB
                       + ((lane >> 3) & 1) * 16;

    load_stage(sb, Af, Bh, Bl, m0, n0, 0, tid);
    CP_COMMIT();

    const int NKT = DV_ / BK;   // 128
    for (int kt = 0; kt < NKT; kt++) {
        if (kt + 1 < NKT) {
            load_stage(sb + ((kt + 1) & 1) * STAGE_B, Af, Bh, Bl,
                       m0, n0, (kt + 1) * BK, tid);
            CP_COMMIT();
            CP_WAIT(1);
        } else {
            CP_WAIT(0);
        }
        __syncthreads();   // stage ready; protects sAhi/sAlo from prev MMA phase

        const char* st = smc + (kt & 1) * STAGE_B;

        // ---- cooperative A split: fp32 tile -> sAhi / sAlo ----
        {
            const float* src = (const float*)st + crow * A_LDF + ccol;
            uint32_t hw[8], lw[8];
#pragma unroll
            for (int j = 0; j < 8; j++) {
                float2 v = *(const float2*)(src + 2 * j);
                splitpair(v, hw[j], lw[j]);
            }
            uint32_t* dh = (uint32_t*)(smc + AH_OFF) + crow * (B_LDT / 2) + (tid & 1) * 8;
            uint32_t* dl = (uint32_t*)(smc + AL_OFF) + crow * (B_LDT / 2) + (tid & 1) * 8;
            *(uint4*)dh       = make_uint4(hw[0], hw[1], hw[2], hw[3]);
            *(uint4*)(dh + 4) = make_uint4(hw[4], hw[5], hw[6], hw[7]);
            *(uint4*)dl       = make_uint4(lw[0], lw[1], lw[2], lw[3]);
            *(uint4*)(dl + 4) = make_uint4(lw[4], lw[5], lw[6], lw[7]);
        }
        __syncthreads();

        uint32_t stg = sb + (kt & 1) * STAGE_B;
        uint32_t aH = sb + AH_OFF + aRowOff;
        uint32_t aL = sb + AL_OFF + aRowOff;
        uint32_t bH = stg + A_TB + bRowOff;
        uint32_t bL = bH + BT_TB;

#pragma unroll
        for (int ks = 0; ks < 2; ks++) {
            uint32_t kso = ks * 32;
            uint32_t bh[8][2], bl[8][2];
#pragma unroll
            for (int nj = 0; nj < 4; nj++) {
                ldsm_x4(bh[2 * nj][0], bh[2 * nj][1], bh[2 * nj + 1][0], bh[2 * nj + 1][1],
                        bH + nj * 16 * B_ROWB + kso);
                ldsm_x4(bl[2 * nj][0], bl[2 * nj][1], bl[2 * nj + 1][0], bl[2 * nj + 1][1],
                        bL + nj * 16 * B_ROWB + kso);
            }
#pragma unroll
            for (int mi = 0; mi < 4; mi++) {
                uint32_t ah[4], al[4];
                ldsm_x4(ah[0], ah[1], ah[2], ah[3], aH + mi * 16 * B_ROWB + kso);
                ldsm_x4(al[0], al[1], al[2], al[3], aL + mi * 16 * B_ROWB + kso);
#pragma unroll
                for (int ni = 0; ni < 8; ni++) mma16816(acc[mi][ni], ah, bh[ni]);
#pragma unroll
                for (int ni = 0; ni < 8; ni++) mma16816(acc[mi][ni], ah, bl[ni]);
#pragma unroll
                for (int ni = 0; ni < 8; ni++) mma16816(acc[mi][ni], al, bh[ni]);
            }
        }
        __syncthreads();
    }

    // epilogue: C[m, n] = acc + bias[n]
#pragma unroll
    for (int mi = 0; mi < 4; mi++) {
        int mA = m0 + wm * 64 + mi * 16 + g;
#pragma unroll
        for (int ni = 0; ni < 8; ni++) {
            int n = n0 + wn * 64 + ni * 8 + tig * 2;
            float b0 = bias[n], b1 = bias[n + 1];
            float2 v0 = make_float2(acc[mi][ni][0] + b0, acc[mi][ni][1] + b1);
            float2 v1 = make_float2(acc[mi][ni][2] + b0, acc[mi][ni][3] + b1);
            *(float2*)&C[(long)mA * D_ + n] = v0;
            *(float2*)&C[(long)(mA + 8) * D_ + n] = v1;
        }
    }
}

// W [K=4096, N=1024] fp32 -> transposed split bf16 [N, K]
__global__ void splitW_kernel(const float* __restrict__ W,
                              __nv_bfloat16* __restrict__ hi, __nv_bfloat16* __restrict__ lo)
{
    __shared__ float t[32][33];
    int k0 = blockIdx.x * 32, n0 = blockIdx.y * 32;
    int tx = threadIdx.x, ty = threadIdx.y;
#pragma unroll
    for (int i = 0; i < 32; i += 8)
        t[ty + i][tx] = W[(long)(k0 + ty + i) * D_ + n0 + tx];
    __syncthreads();
#pragma unroll
    for (int i = 0; i < 32; i += 8) {
        int n = n0 + ty + i, k = k0 + tx;
        float x = t[tx][ty + i];
        __nv_bfloat16 h = __float2bfloat16(x);
        hi[(long)n * DV_ + k] = h;
        lo[(long)n * DV_ + k] = __float2bfloat16(x - __bfloat162float(h));
    }
}

// ---------------- fp32 SGEMM 64x64 tiles (Sr), register-pipelined ----------------
__global__ void sgemm64_bias(const float* __restrict__ A, const float* __restrict__ Bm,
                             const float* __restrict__ bias, float* __restrict__ C,
                             int M, int N, int K)
{
    const int BKs = 16;
    __shared__ float As[BKs][68];
    __shared__ float Bs[BKs][68];

    int tid = threadIdx.x;
    int m0 = blockIdx.y * 64, n0 = blockIdx.x * 64;
    int ty = tid >> 4, tx = tid & 15;

    float acc[4][4];
#pragma unroll
    for (int i = 0; i < 4; i++)
#pragma unroll
        for (int j = 0; j < 4; j++) acc[i][j] = 0.f;

    int arow = tid >> 2, acol = (tid & 3) * 4;
    int brow = tid >> 4, bcol = (tid & 15) * 4;

    // prologue: tile 0 in registers
    float4 ra = *(const float4*)&A[(long)(m0 + arow) * K + acol];
    float4 rb = *(const float4*)&Bm[(long)brow * N + n0 + bcol];

    for (int k0 = 0; k0 < K; k0 += BKs) {
        As[acol + 0][arow] = ra.x; As[acol + 1][arow] = ra.y;
        As[acol + 2][arow] = ra.z; As[acol + 3][arow] = ra.w;
        Bs[brow][bcol + 0] = rb.x; Bs[brow][bcol + 1] = rb.y;
        Bs[brow][bcol + 2] = rb.z; Bs[brow][bcol + 3] = rb.w;
        __syncthreads();

        if (k0 + BKs < K) {  // prefetch next tile while computing
            ra = *(const float4*)&A[(long)(m0 + arow) * K + k0 + BKs + acol];
            rb = *(const float4*)&Bm[(long)(k0 + BKs + brow) * N + n0 + bcol];
        }
#pragma unroll
        for (int kk = 0; kk < BKs; kk++) {
            float4 a = *(const float4*)&As[kk][ty * 4];
            float4 b = *(const float4*)&Bs[kk][tx * 4];
            float av[4] = {a.x, a.y, a.z, a.w};
            float bv[4] = {b.x, b.y, b.z, b.w};
#pragma unroll
            for (int i = 0; i < 4; i++)
#pragma unroll
                for (int j = 0; j < 4; j++) acc[i][j] += av[i] * bv[j];
        }
        __syncthreads();
    }

    float4 bb = *(const float4*)&bias[n0 + tx * 4];
    float bvv[4] = {bb.x, bb.y, bb.z, bb.w};
#pragma unroll
    for (int i = 0; i < 4; i++) {
        float4 o;
        o.x = acc[i][0] + bvv[0]; o.y = acc[i][1] + bvv[1];
        o.z = acc[i][2] + bvv[2]; o.w = acc[i][3] + bvv[3];
        *(float4*)&C[(long)(m0 + ty * 4 + i) * N + n0 + tx * 4] = o;
    }
}

// ---------------- Sr column norms ----------------
__global__ void snorm_kernel()
{
    int id = blockIdx.x * 256 + threadIdx.x;
    int b = id >> 10, d = id & 1023;
    float s = 0.f;
#pragma unroll
    for (int l = 0; l < L_; l++) {
        float v = g_Sr[(b * L_ + l) * D_ + d];
        s += v * v;
    }
    g_snorm[id] = sqrtf(s);
}

// ---------------- scores[b,l,t] = Sr[b,l,:]·Vr[b,t,:] ----------------
__global__ void scores_kernel()
{
    int b = blockIdx.y;
    int t0 = blockIdx.x * 64;
    __shared__ float sS[32][36];
    __shared__ float sV[32][68];
    int tid = threadIdx.x;
    int ty = tid >> 4, tx = tid & 15;
    float acc[2][4] = {{0, 0, 0, 0}, {0, 0, 0, 0}};

    int lrow = tid >> 3, kc = (tid & 7) * 4;
    for (int k0 = 0; k0 < D_; k0 += 32) {
        {
            float4 v = *(const float4*)&g_Sr[(b * L_ + lrow) * D_ + k0 + kc];
            sS[kc + 0][lrow] = v.x; sS[kc + 1][lrow] = v.y;
            sS[kc + 2][lrow] = v.z; sS[kc + 3][lrow] = v.w;
        }
#pragma unroll
        for (int i = 0; i < 2; i++) {
            int tt = lrow + i * 32;
            int t = t0 + tt;
            float4 w = make_float4(0.f, 0.f, 0.f, 0.f);
            if (t < T_) w = *(const float4*)&g_Vr[((long)b * T_ + t) * D_ + k0 + kc];
            sV[kc + 0][tt] = w.x; sV[kc + 1][tt] = w.y;
            sV[kc + 2][tt] = w.z; sV[kc + 3][tt] = w.w;
        }
        __syncthreads();
#pragma unroll
        for (int kk = 0; kk < 32; kk++) {
            float a0 = sS[kk][ty * 2], a1 = sS[kk][ty * 2 + 1];
            float4 bv = *(const float4*)&sV[kk][tx * 4];
            acc[0][0] += a0 * bv.x; acc[0][1] += a0 * bv.y;
            acc[0][2] += a0 * bv.z; acc[0][3] += a0 * bv.w;
            acc[1][0] += a1 * bv.x; acc[1][1] += a1 * bv.y;
            acc[1][2] += a1 * bv.z; acc[1][3] += a1 * bv.w;
        }
        __syncthreads();
    }
#pragma unroll
    for (int i = 0; i < 2; i++) {
        int l = ty * 2 + i;
#pragma unroll
        for (int j = 0; j < 4; j++) {
            int t = t0 + tx * 4 + j;
            if (t < T_) g_scores[(b * L_ + l) * T_ + t] = acc[i][j];
        }
    }
}

// ---------------- per-segment max/Z + exp weights ----------------
__global__ void segprep_kernel()
{
    int bl = blockIdx.x;
    __shared__ float sm[NSEG];
    int tid = threadIdx.x;
    const float* row = g_scores + bl * T_;
    if (tid < NSEG) {
        float mx = -INFINITY;
#pragma unroll
        for (int i = 0; i < FPS_; i++) mx = fmaxf(mx, row[tid * FPS_ + i]);
        float z = 0.f;
#pragma unroll
        for (int i = 0; i < FPS_; i++) z += expf(row[tid * FPS_ + i] - mx);
        sm[tid] = mx;
        g_m[bl * NSEG + tid] = mx;
        g_Zs[bl * NSEG + tid] = z;
    }
    __syncthreads();
    for (int t = tid; t < T_; t += 256)
        g_wtil[bl * T_ + t] = expf(row[t] - sm[t / FPS_]);
}

// ---------------- E[b,l,g,d] = sum_{t in seg g} wtil * Vr[b,t,d] ----------------
__global__ void eagg_kernel()
{
    int dc = blockIdx.x, g = blockIdx.y, b = blockIdx.z;
    int tid = threadIdx.x;
    int d = dc * 256 + tid;
    __shared__ float Vs[FPS_][256];
    __shared__ float ws[L_][FPS_ + 1];
#pragma unroll
    for (int t = 0; t < FPS_; t++)
        Vs[t][tid] = g_Vr[((long)b * T_ + g * FPS_ + t) * D_ + d];
    for (int i = tid; i < L_ * FPS_; i += 256) {
        int l = i / FPS_, t = i % FPS_;
        ws[l][t] = g_wtil[(b * L_ + l) * T_ + g * FPS_ + t];
    }
    __syncthreads();
    for (int l = 0; l < L_; l++) {
        float acc = 0.f;
#pragma unroll
        for (int t = 0; t < FPS_; t++) acc += ws[l][t] * Vs[t][tid];
        g_E[((long)(b * L_ + l) * NSEG + g) * D_ + d] = acc;
    }
}

// ============================================================================
// prop_kernel v3: barrier-free chain streaming.
// ============================================================================
#define PCH 128
__global__ void __launch_bounds__(PCH) prop_kernel(const int* __restrict__ ytrue,
                                                   float* __restrict__ outPos)
{
    int b = blockIdx.y, dc = blockIdx.x, sg = blockIdx.z;
    int tid = threadIdx.x;
    int d = dc * PCH + tid;

    __shared__ float s_m[L_][NSEG], s_Z[L_][NSEG];
    __shared__ float sSr[L_][PCH];
    __shared__ float c_sc[40][L_], c_an[40][L_], c_iz[40][L_];

    for (int i = tid; i < L_ * NSEG; i += PCH) {
        int l = i >> 4, g = i & 15;
        s_m[l][g] = g_m[(b * L_ + l) * NSEG + g];
        s_Z[l][g] = g_Zs[(b * L_ + l) * NSEG + g];
    }
    for (int i = tid; i < L_ * PCH; i += PCH) {
        int l = i / PCH, j = i % PCH;
        sSr[l][j] = g_Sr[(b * L_ + l) * D_ + dc * PCH + j];
    }
    __syncthreads();

    {
        int l = tid & 31, ci = tid >> 5;
        int s = sg + 4 * ci;
        int base = 0;
#pragma unroll
        for (int j = 0; j < 4; j++) if (j < ci) base += NSEG - (sg + 4 * j);
        float M = s_m[l][s], Zw = s_Z[l][s];
        c_sc[base][l] = 0.f; c_an[base][l] = 1.f; c_iz[base][l] = 1.f / Zw;
        for (int e = s + 1; e < NSEG; e++) {
            float mv = s_m[l][e];
            float Mn = fmaxf(M, mv);
            float sc = expf(M - Mn), an = expf(mv - Mn);
            Zw = Zw * sc + an * s_Z[l][e];
            M = Mn;
            int st = base + e - s;
            c_sc[st][l] = sc; c_an[st][l] = an; c_iz[st][l] = 1.f / Zw;
        }
    }
    __syncthreads();

    float sn = g_snorm[b * D_ + d];
    int ys = ytrue[2 * b], ye = ytrue[2 * b + 1];
    float negmax = -INFINITY;

    int base = 0;
#pragma unroll 1
    for (int ci = 0; ci < 4; ci++) {
        int s = sg + 4 * ci;
        float U[L_];
#pragma unroll
        for (int l = 0; l < L_; l++) U[l] = 0.f;
#pragma unroll 1
        for (int e = s; e < NSEG; e++) {
            int st = base + e - s;
            float num = 0.f, sq = 0.f;
            const float* Eb = g_E + ((long)(b * L_) * NSEG + e) * D_ + d;
#pragma unroll
            for (int l = 0; l < L_; l++) {
                float Ev = Eb[(long)l * NSEG * D_];
                float u = U[l] * c_sc[st][l] + c_an[st][l] * Ev;
                U[l] = u;
                float o = u * c_iz[st][l];
                num += o * sSr[l][tid];
                sq += o * o;
            }
            float scv = num / (sqrtf(sq) * sn + 1e-15f);
            if (s == ys && e == ye) outPos[b * D_ + d] = scv;
            else negmax = fmaxf(negmax, scv);
        }
        base += NSEG - s;
    }

#pragma unroll
    for (int off = 16; off; off >>= 1)
        negmax = fmaxf(negmax, __shfl_xor_sync(0xffffffffu, negmax, off));
    __shared__ float wm[4];
    if ((tid & 31) == 0) wm[tid >> 5] = negmax;
    __syncthreads();
    if (tid == 0) {
        float v = fmaxf(fmaxf(wm[0], wm[1]), fmaxf(wm[2], wm[3]));
        unsigned u = __float_as_uint(v);
        u = (u & 0x80000000u) ? ~u : (u | 0x80000000u);
        atomicMax(&g_negmax[b], u);
    }
}

__global__ void init_neg()
{
    if (threadIdx.x < B_) g_negmax[threadIdx.x] = 0x007FFFFFu;
}

__global__ void fin_kernel(float* __restrict__ outNeg)
{
    int b = threadIdx.x;
    if (b < B_) {
        unsigned u = g_negmax[b];
        unsigned bits = (u & 0x80000000u) ? (u ^ 0x80000000u) : ~u;
        outNeg[b] = __uint_as_float(bits);
    }
}

// ---------------- launch ----------------
extern "C" void kernel_launch(void* const* d_in, const int* in_sizes, int n_in,
                              void* d_out, int out_size)
{
    const float* videos    = (const float*)d_in[0];
    const float* sentences = (const float*)d_in[1];
    const float* Wv        = (const float*)d_in[2];
    const float* bv        = (const float*)d_in[3];
    const float* Ws        = (const float*)d_in[4];
    const float* bs        = (const float*)d_in[5];
    const int*   ytrue     = (const int*)d_in[6];
    float* out = (float*)d_out;

    float *pVr = nullptr, *pSr = nullptr;
    void *pBhi = nullptr, *pBlo = nullptr;
    cudaGetSymbolAddress((void**)&pVr, g_Vr);
    cudaGetSymbolAddress((void**)&pSr, g_Sr);
    cudaGetSymbolAddress(&pBhi, g_Bhi);
    cudaGetSymbolAddress(&pBlo, g_Blo);

    cudaFuncSetAttribute(vr_gemm, cudaFuncAttributeMaxDynamicSharedMemorySize, GEMM_SMEM);

    init_neg<<<1, 32>>>();                                              // 1
    splitW_kernel<<<dim3(DV_ / 32, D_ / 32), dim3(32, 8)>>>(Wv,         // 2
        (__nv_bfloat16*)pBhi, (__nv_bfloat16*)pBlo);
    sgemm64_bias<<<dim3(D_ / 64, (B_ * L_) / 64), 256>>>(sentences,     // 3
        Ws, bs, pSr, B_ * L_, D_, DS_);
    vr_gemm<<<dim3(D_ / 256, (B_ * T_) / 128), 256, GEMM_SMEM>>>(       // 4 (profiled)
        videos, (const __nv_bfloat16*)pBhi, (const __nv_bfloat16*)pBlo, bv, pVr);

    snorm_kernel<<<(B_ * D_) / 256, 256>>>();
    scores_kernel<<<dim3((T_ + 63) / 64, B_), 256>>>();
    segprep_kernel<<<B_ * L_, 256>>>();
    eagg_kernel<<<dim3(D_ / 256, NSEG, B_), 256>>>();
    prop_kernel<<<dim3(D_ / PCH, B_, 4), PCH>>>(ytrue, out);
    fin_kernel<<<1, 32>>>(out + B_ * D_);
}

// round 11
// speedup vs baseline: 1.4608x; 1.2527x over previous
#include <cuda_runtime.h>
#include <cuda_bf16.h>
#include <math.h>
#include <stdint.h>

#define B_    16
#define T_    400
#define DV_   4096
#define DS_   768
#define D_    1024
#define L_    32
#define NSEG  16
#define FPS_  25
#define NPROP 136

// ---------------- scratch (static device globals; no allocation) ----------------
__device__ float    g_Vr[B_ * T_ * D_];          // 26.2 MB
__device__ float    g_Sr[B_ * L_ * D_];          // 2.1 MB
__device__ float    g_scores[B_ * L_ * T_];
__device__ float    g_wtil[B_ * L_ * T_];
__device__ float    g_m[B_ * L_ * NSEG];
__device__ float    g_Zs[B_ * L_ * NSEG];
__device__ float    g_E[B_ * L_ * NSEG * D_];    // 33.5 MB
__device__ float    g_snorm[B_ * D_];
__device__ unsigned g_negmax[B_];

// split-bf16 W for the big GEMM (A split is fused into the GEMM)
__device__ __align__(16) __nv_bfloat16 g_Bhi[(long)D_ * DV_];       // [N,K]
__device__ __align__(16) __nv_bfloat16 g_Blo[(long)D_ * DV_];

// ---------------- helpers ----------------
__device__ __forceinline__ uint32_t smem_u32(const void* p) {
    uint32_t a;
    asm("{ .reg .u64 t; cvta.to.shared.u64 t, %1; cvt.u32.u64 %0, t; }" : "=r"(a) : "l"(p));
    return a;
}
#define CP_ASYNC16(dst, src) \
    asm volatile("cp.async.cg.shared.global [%0], [%1], 16;" :: "r"(dst), "l"(src) : "memory")
#define CP_COMMIT() asm volatile("cp.async.commit_group;" ::: "memory")
#define CP_WAIT(n)  asm volatile("cp.async.wait_group %0;" :: "n"(n) : "memory")

__device__ __forceinline__ void mma16816(float* c, const uint32_t* a, const uint32_t* b) {
    asm volatile(
        "mma.sync.aligned.m16n8k16.row.col.f32.bf16.bf16.f32 "
        "{%0,%1,%2,%3}, {%4,%5,%6,%7}, {%8,%9}, {%0,%1,%2,%3};"
        : "+f"(c[0]), "+f"(c[1]), "+f"(c[2]), "+f"(c[3])
        : "r"(a[0]), "r"(a[1]), "r"(a[2]), "r"(a[3]), "r"(b[0]), "r"(b[1]));
}

__device__ __forceinline__ void ldsm_x4(uint32_t& r0, uint32_t& r1, uint32_t& r2,
                                        uint32_t& r3, uint32_t addr) {
    asm volatile("ldmatrix.sync.aligned.m8n8.x4.shared.b16 {%0,%1,%2,%3}, [%4];"
                 : "=r"(r0), "=r"(r1), "=r"(r2), "=r"(r3) : "r"(addr));
}

// split a float2 into packed bf16x2 (hi) and packed bf16x2 (residual lo)
__device__ __forceinline__ void splitpair(float2 v, uint32_t& h, uint32_t& l) {
    __nv_bfloat162 hb = __floats2bfloat162_rn(v.x, v.y);   // .x = low half = elem k
    float2 hf = __bfloat1622float2(hb);
    __nv_bfloat162 lb = __floats2bfloat162_rn(v.x - hf.x, v.y - hf.y);
    h = *(uint32_t*)&hb;
    l = *(uint32_t*)&lb;
}

// ============================================================================
// Vr GEMM (R8-proven config): C = A_fp32 @ B(split bf16)^T + bias
// 128x128 tile, BK=32, 2-stage cp.async; A split staged in smem once per tile;
// ldmatrix fragment loads; term-pass mma order; 2 CTAs/SM.
// ============================================================================
#define BK      32
#define A_LDF   36                          // fp32 per A smem row (32 + 4 pad)
#define A_TB    (128 * A_LDF * 4)           // 18432 bytes (fp32 A stage)
#define B_LDT   40                          // bf16 per smem row (32 + 8 pad)
#define B_ROWB  (B_LDT * 2)                 // 80 bytes per row
#define B_TB    (128 * B_ROWB)              // 10240 bytes per bf16 matrix tile
#define STAGE_B (A_TB + 2 * B_TB)           // 38912
#define AH_OFF  (2 * STAGE_B)               // 77824 (single converted-A buffer)
#define AL_OFF  (AH_OFF + B_TB)             // 88064
#define GEMM_SMEM (AL_OFF + B_TB)           // 98304

__device__ __forceinline__ void load_stage(
    uint32_t sbase, const float* __restrict__ Af,
    const __nv_bfloat16* __restrict__ Bh, const __nv_bfloat16* __restrict__ Bl,
    int m0, int n0, int k0, int tid)
{
#pragma unroll
    for (int i = 0; i < 4; i++) {
        int c = i * 256 + tid;
        int row = c >> 3, ch = c & 7;
        CP_ASYNC16(sbase + row * (A_LDF * 4) + ch * 16,
                   Af + (long)(m0 + row) * DV_ + k0 + ch * 4);
    }
#pragma unroll
    for (int i = 0; i < 2; i++) {
        int c = i * 256 + tid;
        int row = c >> 2, ch = c & 3;
        long roff = (long)(n0 + row) * DV_ + k0 + ch * 8;
        uint32_t dd = row * B_ROWB + ch * 16;
        CP_ASYNC16(sbase + A_TB + dd, Bh + roff);
        CP_ASYNC16(sbase + A_TB + B_TB + dd, Bl + roff);
    }
}

__global__ void __launch_bounds__(256, 2) vr_gemm(
    const float* __restrict__ Af,
    const __nv_bfloat16* __restrict__ Bh, const __nv_bfloat16* __restrict__ Bl,
    const float* __restrict__ bias, float* __restrict__ C)
{
    extern __shared__ char smc[];
    uint32_t sb = smem_u32(smc);
    int tid = threadIdx.x, wid = tid >> 5, lane = tid & 31;
    int g = lane >> 2, tig = lane & 3;
    int wm = wid >> 2, wn = wid & 3;          // 2 x 4 warp grid
    int n0 = blockIdx.x * 128, m0 = blockIdx.y * 128;

    float acc[4][4][4];
#pragma unroll
    for (int a = 0; a < 4; a++)
#pragma unroll
        for (int b = 0; b < 4; b++)
#pragma unroll
            for (int cc = 0; cc < 4; cc++) acc[a][b][cc] = 0.f;

    // conversion-phase indices
    int crow = tid >> 1, ccol = (tid & 1) * 16;

    // ldmatrix per-thread base offsets
    uint32_t aRowOff = (uint32_t)(wm * 64 + (lane & 15)) * B_ROWB + (lane >> 4) * 16;
    uint32_t bRowOff = (uint32_t)(wn * 32 + (lane >> 4) * 8 + (lane & 7)) * B_ROWB
                       + ((lane >> 3) & 1) * 16;

    load_stage(sb, Af, Bh, Bl, m0, n0, 0, tid);
    CP_COMMIT();

    const int NKT = DV_ / BK;   // 128
    for (int kt = 0; kt < NKT; kt++) {
        if (kt + 1 < NKT) {
            load_stage(sb + ((kt + 1) & 1) * STAGE_B, Af, Bh, Bl,
                       m0, n0, (kt + 1) * BK, tid);
            CP_COMMIT();
            CP_WAIT(1);
        } else {
            CP_WAIT(0);
        }
        __syncthreads();   // stage ready; protects sAhi/sAlo from prev MMA phase

        const char* st = smc + (kt & 1) * STAGE_B;

        // ---- cooperative A split: fp32 tile -> sAhi / sAlo ----
        {
            const float* src = (const float*)st + crow * A_LDF + ccol;
            uint32_t hw[8], lw[8];
#pragma unroll
            for (int j = 0; j < 8; j++) {
                float2 v = *(const float2*)(src + 2 * j);
                splitpair(v, hw[j], lw[j]);
            }
            uint32_t* dh = (uint32_t*)(smc + AH_OFF) + crow * (B_LDT / 2) + (tid & 1) * 8;
            uint32_t* dl = (uint32_t*)(smc + AL_OFF) + crow * (B_LDT / 2) + (tid & 1) * 8;
            *(uint4*)dh       = make_uint4(hw[0], hw[1], hw[2], hw[3]);
            *(uint4*)(dh + 4) = make_uint4(hw[4], hw[5], hw[6], hw[7]);
            *(uint4*)dl       = make_uint4(lw[0], lw[1], lw[2], lw[3]);
            *(uint4*)(dl + 4) = make_uint4(lw[4], lw[5], lw[6], lw[7]);
        }
        __syncthreads();

        uint32_t aH = sb + AH_OFF + aRowOff;
        uint32_t aL = sb + AL_OFF + aRowOff;
        uint32_t bH = sb + (kt & 1) * STAGE_B + A_TB + bRowOff;
        uint32_t bL = bH + B_TB;

#pragma unroll
        for (int ks = 0; ks < 2; ks++) {
            uint32_t kso = ks * 32;           // 16 bf16 = 32B per k-chunk
            uint32_t bh[4][2], bl[4][2];
            ldsm_x4(bh[0][0], bh[0][1], bh[1][0], bh[1][1], bH + kso);
            ldsm_x4(bh[2][0], bh[2][1], bh[3][0], bh[3][1], bH + 16 * B_ROWB + kso);
            ldsm_x4(bl[0][0], bl[0][1], bl[1][0], bl[1][1], bL + kso);
            ldsm_x4(bl[2][0], bl[2][1], bl[3][0], bl[3][1], bL + 16 * B_ROWB + kso);
#pragma unroll
            for (int mi = 0; mi < 4; mi++) {
                uint32_t ah[4], al[4];
                ldsm_x4(ah[0], ah[1], ah[2], ah[3], aH + mi * 16 * B_ROWB + kso);
                ldsm_x4(al[0], al[1], al[2], al[3], aL + mi * 16 * B_ROWB + kso);
#pragma unroll
                for (int ni = 0; ni < 4; ni++) mma16816(acc[mi][ni], ah, bh[ni]);
#pragma unroll
                for (int ni = 0; ni < 4; ni++) mma16816(acc[mi][ni], ah, bl[ni]);
#pragma unroll
                for (int ni = 0; ni < 4; ni++) mma16816(acc[mi][ni], al, bh[ni]);
            }
        }
        __syncthreads();
    }

    // epilogue: C[m, n] = acc + bias[n]
#pragma unroll
    for (int mi = 0; mi < 4; mi++) {
        int mA = m0 + wm * 64 + mi * 16 + g;
#pragma unroll
        for (int ni = 0; ni < 4; ni++) {
            int n = n0 + wn * 32 + ni * 8 + tig * 2;
            float b0 = bias[n], b1 = bias[n + 1];
            float2 v0 = make_float2(acc[mi][ni][0] + b0, acc[mi][ni][1] + b1);
            float2 v1 = make_float2(acc[mi][ni][2] + b0, acc[mi][ni][3] + b1);
            *(float2*)&C[(long)mA * D_ + n] = v0;
            *(float2*)&C[(long)(mA + 8) * D_ + n] = v1;
        }
    }
}

// W [K=4096, N=1024] fp32 -> transposed split bf16 [N, K]
__global__ void splitW_kernel(const float* __restrict__ W,
                              __nv_bfloat16* __restrict__ hi, __nv_bfloat16* __restrict__ lo)
{
    __shared__ float t[32][33];
    int k0 = blockIdx.x * 32, n0 = blockIdx.y * 32;
    int tx = threadIdx.x, ty = threadIdx.y;
#pragma unroll
    for (int i = 0; i < 32; i += 8)
        t[ty + i][tx] = W[(long)(k0 + ty + i) * D_ + n0 + tx];
    __syncthreads();
#pragma unroll
    for (int i = 0; i < 32; i += 8) {
        int n = n0 + ty + i, k = k0 + tx;
        float x = t[tx][ty + i];
        __nv_bfloat16 h = __float2bfloat16(x);
        hi[(long)n * DV_ + k] = h;
        lo[(long)n * DV_ + k] = __float2bfloat16(x - __bfloat162float(h));
    }
}

// ---------------- fp32 SGEMM 64x64 tiles (Sr), register-pipelined ----------------
__global__ void sgemm64_bias(const float* __restrict__ A, const float* __restrict__ Bm,
                             const float* __restrict__ bias, float* __restrict__ C,
                             int M, int N, int K)
{
    const int BKs = 16;
    __shared__ float As[BKs][68];
    __shared__ float Bs[BKs][68];

    int tid = threadIdx.x;
    int m0 = blockIdx.y * 64, n0 = blockIdx.x * 64;
    int ty = tid >> 4, tx = tid & 15;

    float acc[4][4];
#pragma unroll
    for (int i = 0; i < 4; i++)
#pragma unroll
        for (int j = 0; j < 4; j++) acc[i][j] = 0.f;

    int arow = tid >> 2, acol = (tid & 3) * 4;
    int brow = tid >> 4, bcol = (tid & 15) * 4;

    // prologue: tile 0 in registers
    float4 ra = *(const float4*)&A[(long)(m0 + arow) * K + acol];
    float4 rb = *(const float4*)&Bm[(long)brow * N + n0 + bcol];

    for (int k0 = 0; k0 < K; k0 += BKs) {
        As[acol + 0][arow] = ra.x; As[acol + 1][arow] = ra.y;
        As[acol + 2][arow] = ra.z; As[acol + 3][arow] = ra.w;
        Bs[brow][bcol + 0] = rb.x; Bs[brow][bcol + 1] = rb.y;
        Bs[brow][bcol + 2] = rb.z; Bs[brow][bcol + 3] = rb.w;
        __syncthreads();

        if (k0 + BKs < K) {  // prefetch next tile while computing
            ra = *(const float4*)&A[(long)(m0 + arow) * K + k0 + BKs + acol];
            rb = *(const float4*)&Bm[(long)(k0 + BKs + brow) * N + n0 + bcol];
        }
#pragma unroll
        for (int kk = 0; kk < BKs; kk++) {
            float4 a = *(const float4*)&As[kk][ty * 4];
            float4 b = *(const float4*)&Bs[kk][tx * 4];
            float av[4] = {a.x, a.y, a.z, a.w};
            float bv[4] = {b.x, b.y, b.z, b.w};
#pragma unroll
            for (int i = 0; i < 4; i++)
#pragma unroll
                for (int j = 0; j < 4; j++) acc[i][j] += av[i] * bv[j];
        }
        __syncthreads();
    }

    float4 bb = *(const float4*)&bias[n0 + tx * 4];
    float bvv[4] = {bb.x, bb.y, bb.z, bb.w};
#pragma unroll
    for (int i = 0; i < 4; i++) {
        float4 o;
        o.x = acc[i][0] + bvv[0]; o.y = acc[i][1] + bvv[1];
        o.z = acc[i][2] + bvv[2]; o.w = acc[i][3] + bvv[3];
        *(float4*)&C[(long)(m0 + ty * 4 + i) * N + n0 + tx * 4] = o;
    }
}

// ---------------- Sr column norms ----------------
__global__ void snorm_kernel()
{
    int id = blockIdx.x * 256 + threadIdx.x;
    int b = id >> 10, d = id & 1023;
    float s = 0.f;
#pragma unroll
    for (int l = 0; l < L_; l++) {
        float v = g_Sr[(b * L_ + l) * D_ + d];
        s += v * v;
    }
    g_snorm[id] = sqrtf(s);
}

// ---------------- scores[b,l,t] = Sr[b,l,:]·Vr[b,t,:] ----------------
__global__ void scores_kernel()
{
    int b = blockIdx.y;
    int t0 = blockIdx.x * 64;
    __shared__ float sS[32][36];
    __shared__ float sV[32][68];
    int tid = threadIdx.x;
    int ty = tid >> 4, tx = tid & 15;
    float acc[2][4] = {{0, 0, 0, 0}, {0, 0, 0, 0}};

    int lrow = tid >> 3, kc = (tid & 7) * 4;
    for (int k0 = 0; k0 < D_; k0 += 32) {
        {
            float4 v = *(const float4*)&g_Sr[(b * L_ + lrow) * D_ + k0 + kc];
            sS[kc + 0][lrow] = v.x; sS[kc + 1][lrow] = v.y;
            sS[kc + 2][lrow] = v.z; sS[kc + 3][lrow] = v.w;
        }
#pragma unroll
        for (int i = 0; i < 2; i++) {
            int tt = lrow + i * 32;
            int t = t0 + tt;
            float4 w = make_float4(0.f, 0.f, 0.f, 0.f);
            if (t < T_) w = *(const float4*)&g_Vr[((long)b * T_ + t) * D_ + k0 + kc];
            sV[kc + 0][tt] = w.x; sV[kc + 1][tt] = w.y;
            sV[kc + 2][tt] = w.z; sV[kc + 3][tt] = w.w;
        }
        __syncthreads();
#pragma unroll
        for (int kk = 0; kk < 32; kk++) {
            float a0 = sS[kk][ty * 2], a1 = sS[kk][ty * 2 + 1];
            float4 bv = *(const float4*)&sV[kk][tx * 4];
            acc[0][0] += a0 * bv.x; acc[0][1] += a0 * bv.y;
            acc[0][2] += a0 * bv.z; acc[0][3] += a0 * bv.w;
            acc[1][0] += a1 * bv.x; acc[1][1] += a1 * bv.y;
            acc[1][2] += a1 * bv.z; acc[1][3] += a1 * bv.w;
        }
        __syncthreads();
    }
#pragma unroll
    for (int i = 0; i < 2; i++) {
        int l = ty * 2 + i;
#pragma unroll
        for (int j = 0; j < 4; j++) {
            int t = t0 + tx * 4 + j;
            if (t < T_) g_scores[(b * L_ + l) * T_ + t] = acc[i][j];
        }
    }
}

// ---------------- per-segment max/Z + exp weights ----------------
__global__ void segprep_kernel()
{
    int bl = blockIdx.x;
    __shared__ float sm[NSEG];
    int tid = threadIdx.x;
    const float* row = g_scores + bl * T_;
    if (tid < NSEG) {
        float mx = -INFINITY;
#pragma unroll
        for (int i = 0; i < FPS_; i++) mx = fmaxf(mx, row[tid * FPS_ + i]);
        float z = 0.f;
#pragma unroll
        for (int i = 0; i < FPS_; i++) z += expf(row[tid * FPS_ + i] - mx);
        sm[tid] = mx;
        g_m[bl * NSEG + tid] = mx;
        g_Zs[bl * NSEG + tid] = z;
    }
    __syncthreads();
    for (int t = tid; t < T_; t += 256)
        g_wtil[bl * T_ + t] = expf(row[t] - sm[t / FPS_]);
}

// ---------------- E[b,l,g,d] = sum_{t in seg g} wtil * Vr[b,t,d] ----------------
__global__ void eagg_kernel()
{
    int dc = blockIdx.x, g = blockIdx.y, b = blockIdx.z;
    int tid = threadIdx.x;
    int d = dc * 256 + tid;
    __shared__ float Vs[FPS_][256];
    __shared__ float ws[L_][FPS_ + 1];
#pragma unroll
    for (int t = 0; t < FPS_; t++)
        Vs[t][tid] = g_Vr[((long)b * T_ + g * FPS_ + t) * D_ + d];
    for (int i = tid; i < L_ * FPS_; i += 256) {
        int l = i / FPS_, t = i % FPS_;
        ws[l][t] = g_wtil[(b * L_ + l) * T_ + g * FPS_ + t];
    }
    __syncthreads();
    for (int l = 0; l < L_; l++) {
        float acc = 0.f;
#pragma unroll
        for (int t = 0; t < FPS_; t++) acc += ws[l][t] * Vs[t][tid];
        g_E[((long)(b * L_ + l) * NSEG + g) * D_ + d] = acc;
    }
}

// ============================================================================
// prop_kernel v3: barrier-free chain streaming.
// ============================================================================
#define PCH 128
__global__ void __launch_bounds__(PCH) prop_kernel(const int* __restrict__ ytrue,
                                                   float* __restrict__ outPos)
{
    int b = blockIdx.y, dc = blockIdx.x, sg = blockIdx.z;
    int tid = threadIdx.x;
    int d = dc * PCH + tid;

    __shared__ float s_m[L_][NSEG], s_Z[L_][NSEG];
    __shared__ float sSr[L_][PCH];
    __shared__ float c_sc[40][L_], c_an[40][L_], c_iz[40][L_];

    for (int i = tid; i < L_ * NSEG; i += PCH) {
        int l = i >> 4, g = i & 15;
        s_m[l][g] = g_m[(b * L_ + l) * NSEG + g];
        s_Z[l][g] = g_Zs[(b * L_ + l) * NSEG + g];
    }
    for (int i = tid; i < L_ * PCH; i += PCH) {
        int l = i / PCH, j = i % PCH;
        sSr[l][j] = g_Sr[(b * L_ + l) * D_ + dc * PCH + j];
    }
    __syncthreads();

    {
        int l = tid & 31, ci = tid >> 5;
        int s = sg + 4 * ci;
        int base = 0;
#pragma unroll
        for (int j = 0; j < 4; j++) if (j < ci) base += NSEG - (sg + 4 * j);
        float M = s_m[l][s], Zw = s_Z[l][s];
        c_sc[base][l] = 0.f; c_an[base][l] = 1.f; c_iz[base][l] = 1.f / Zw;
        for (int e = s + 1; e < NSEG; e++) {
            float mv = s_m[l][e];
            float Mn = fmaxf(M, mv);
            float sc = expf(M - Mn), an = expf(mv - Mn);
            Zw = Zw * sc + an * s_Z[l][e];
            M = Mn;
            int st = base + e - s;
            c_sc[st][l] = sc; c_an[st][l] = an; c_iz[st][l] = 1.f / Zw;
        }
    }
    __syncthreads();

    float sn = g_snorm[b * D_ + d];
    int ys = ytrue[2 * b], ye = ytrue[2 * b + 1];
    float negmax = -INFINITY;

    int base = 0;
#pragma unroll 1
    for (int ci = 0; ci < 4; ci++) {
        int s = sg + 4 * ci;
        float U[L_];
#pragma unroll
        for (int l = 0; l < L_; l++) U[l] = 0.f;
#pragma unroll 1
        for (int e = s; e < NSEG; e++) {
            int st = base + e - s;
            float num = 0.f, sq = 0.f;
            const float* Eb = g_E + ((long)(b * L_) * NSEG + e) * D_ + d;
#pragma unroll
            for (int l = 0; l < L_; l++) {
                float Ev = Eb[(long)l * NSEG * D_];
                float u = U[l] * c_sc[st][l] + c_an[st][l] * Ev;
                U[l] = u;
                float o = u * c_iz[st][l];
                num += o * sSr[l][tid];
                sq += o * o;
            }
            float scv = num / (sqrtf(sq) * sn + 1e-15f);
            if (s == ys && e == ye) outPos[b * D_ + d] = scv;
            else negmax = fmaxf(negmax, scv);
        }
        base += NSEG - s;
    }

#pragma unroll
    for (int off = 16; off; off >>= 1)
        negmax = fmaxf(negmax, __shfl_xor_sync(0xffffffffu, negmax, off));
    __shared__ float wm[4];
    if ((tid & 31) == 0) wm[tid >> 5] = negmax;
    __syncthreads();
    if (tid == 0) {
        float v = fmaxf(fmaxf(wm[0], wm[1]), fmaxf(wm[2], wm[3]));
        unsigned u = __float_as_uint(v);
        u = (u & 0x80000000u) ? ~u : (u | 0x80000000u);
        atomicMax(&g_negmax[b], u);
    }
}

__global__ void init_neg()
{
    if (threadIdx.x < B_) g_negmax[threadIdx.x] = 0x007FFFFFu;
}

__global__ void fin_kernel(float* __restrict__ outNeg)
{
    int b = threadIdx.x;
    if (b < B_) {
        unsigned u = g_negmax[b];
        unsigned bits = (u & 0x80000000u) ? (u ^ 0x80000000u) : ~u;
        outNeg[b] = __uint_as_float(bits);
    }
}

// ---------------- launch ----------------
extern "C" void kernel_launch(void* const* d_in, const int* in_sizes, int n_in,
                              void* d_out, int out_size)
{
    const float* videos    = (const float*)d_in[0];
    const float* sentences = (const float*)d_in[1];
    const float* Wv        = (const float*)d_in[2];
    const float* bv        = (const float*)d_in[3];
    const float* Ws        = (const float*)d_in[4];
    const float* bs        = (const float*)d_in[5];
    const int*   ytrue     = (const int*)d_in[6];
    float* out = (float*)d_out;

    float *pVr = nullptr, *pSr = nullptr;
    void *pBhi = nullptr, *pBlo = nullptr;
    cudaGetSymbolAddress((void**)&pVr, g_Vr);
    cudaGetSymbolAddress((void**)&pSr, g_Sr);
    cudaGetSymbolAddress(&pBhi, g_Bhi);
    cudaGetSymbolAddress(&pBlo, g_Blo);

    cudaFuncSetAttribute(vr_gemm, cudaFuncAttributeMaxDynamicSharedMemorySize, GEMM_SMEM);

    init_neg<<<1, 32>>>();                                              // 1
    splitW_kernel<<<dim3(DV_ / 32, D_ / 32), dim3(32, 8)>>>(Wv,         // 2
        (__nv_bfloat16*)pBhi, (__nv_bfloat16*)pBlo);
    sgemm64_bias<<<dim3(D_ / 64, (B_ * L_) / 64), 256>>>(sentences,     // 3
        Ws, bs, pSr, B_ * L_, D_, DS_);
    vr_gemm<<<dim3(D_ / 128, (B_ * T_) / 128), 256, GEMM_SMEM>>>(       // 4 (profiled)
        videos, (const __nv_bfloat16*)pBhi, (const __nv_bfloat16*)pBlo, bv, pVr);

    snorm_kernel<<<(B_ * D_) / 256, 256>>>();
    scores_kernel<<<dim3((T_ + 63) / 64, B_), 256>>>();
    segprep_kernel<<<B_ * L_, 256>>>();
    eagg_kernel<<<dim3(D_ / 256, NSEG, B_), 256>>>();
    prop_kernel<<<dim3(D_ / PCH, B_, 4), PCH>>>(ytrue, out);
    fin_kernel<<<1, 32>>>(out + B_ * D_);
}

// round 12
// speedup vs baseline: 1.4857x; 1.0171x over previous
#include <cuda_runtime.h>
#include <cuda_bf16.h>
#include <math.h>
#include <stdint.h>

#define B_    16
#define T_    400
#define DV_   4096
#define DS_   768
#define D_    1024
#define L_    32
#define NSEG  16
#define FPS_  25
#define NPROP 136

// ---------------- scratch (static device globals; no allocation) ----------------
__device__ float    g_Vr[B_ * T_ * D_];          // 26.2 MB
__device__ float    g_Sr[B_ * L_ * D_];          // 2.1 MB
__device__ float    g_scores[B_ * L_ * T_];
__device__ float    g_wtil[B_ * L_ * T_];
__device__ float    g_m[B_ * L_ * NSEG];
__device__ float    g_Zs[B_ * L_ * NSEG];
__device__ float    g_E[B_ * L_ * NSEG * D_];    // 33.5 MB
__device__ float    g_snorm[B_ * D_];
__device__ unsigned g_negmax[B_];

// split-bf16 W for the big GEMM (A split is fused into the GEMM)
__device__ __align__(16) __nv_bfloat16 g_Bhi[(long)D_ * DV_];       // [N,K]
__device__ __align__(16) __nv_bfloat16 g_Blo[(long)D_ * DV_];

// ---------------- helpers ----------------
__device__ __forceinline__ uint32_t smem_u32(const void* p) {
    uint32_t a;
    asm("{ .reg .u64 t; cvta.to.shared.u64 t, %1; cvt.u32.u64 %0, t; }" : "=r"(a) : "l"(p));
    return a;
}
#define CP_ASYNC16(dst, src) \
    asm volatile("cp.async.cg.shared.global [%0], [%1], 16;" :: "r"(dst), "l"(src) : "memory")
#define CP_COMMIT() asm volatile("cp.async.commit_group;" ::: "memory")
#define CP_WAIT(n)  asm volatile("cp.async.wait_group %0;" :: "n"(n) : "memory")

__device__ __forceinline__ void mma16816(float* c, const uint32_t* a, const uint32_t* b) {
    asm volatile(
        "mma.sync.aligned.m16n8k16.row.col.f32.bf16.bf16.f32 "
        "{%0,%1,%2,%3}, {%4,%5,%6,%7}, {%8,%9}, {%0,%1,%2,%3};"
        : "+f"(c[0]), "+f"(c[1]), "+f"(c[2]), "+f"(c[3])
        : "r"(a[0]), "r"(a[1]), "r"(a[2]), "r"(a[3]), "r"(b[0]), "r"(b[1]));
}

__device__ __forceinline__ void ldsm_x4(uint32_t& r0, uint32_t& r1, uint32_t& r2,
                                        uint32_t& r3, uint32_t addr) {
    asm volatile("ldmatrix.sync.aligned.m8n8.x4.shared.b16 {%0,%1,%2,%3}, [%4];"
                 : "=r"(r0), "=r"(r1), "=r"(r2), "=r"(r3) : "r"(addr));
}

// split a float2 into packed bf16x2 (hi) and packed bf16x2 (residual lo)
__device__ __forceinline__ void splitpair(float2 v, uint32_t& h, uint32_t& l) {
    __nv_bfloat162 hb = __floats2bfloat162_rn(v.x, v.y);   // .x = low half = elem k
    float2 hf = __bfloat1622float2(hb);
    __nv_bfloat162 lb = __floats2bfloat162_rn(v.x - hf.x, v.y - hf.y);
    h = *(uint32_t*)&hb;
    l = *(uint32_t*)&lb;
}

// ============================================================================
// Vr GEMM (R8-proven config): C = A_fp32 @ B(split bf16)^T + bias
// 128x128 tile, BK=32, 2-stage cp.async; A split staged in smem once per tile;
// ldmatrix fragment loads; term-pass mma order; 2 CTAs/SM.
// ============================================================================
#define BK      32
#define A_LDF   36                          // fp32 per A smem row (32 + 4 pad)
#define A_TB    (128 * A_LDF * 4)           // 18432 bytes (fp32 A stage)
#define B_LDT   40                          // bf16 per smem row (32 + 8 pad)
#define B_ROWB  (B_LDT * 2)                 // 80 bytes per row
#define B_TB    (128 * B_ROWB)              // 10240 bytes per bf16 matrix tile
#define STAGE_B (A_TB + 2 * B_TB)           // 38912
#define AH_OFF  (2 * STAGE_B)               // 77824 (single converted-A buffer)
#define AL_OFF  (AH_OFF + B_TB)             // 88064
#define GEMM_SMEM (AL_OFF + B_TB)           // 98304

__device__ __forceinline__ void load_stage(
    uint32_t sbase, const float* __restrict__ Af,
    const __nv_bfloat16* __restrict__ Bh, const __nv_bfloat16* __restrict__ Bl,
    int m0, int n0, int k0, int tid)
{
#pragma unroll
    for (int i = 0; i < 4; i++) {
        int c = i * 256 + tid;
        int row = c >> 3, ch = c & 7;
        CP_ASYNC16(sbase + row * (A_LDF * 4) + ch * 16,
                   Af + (long)(m0 + row) * DV_ + k0 + ch * 4);
    }
#pragma unroll
    for (int i = 0; i < 2; i++) {
        int c = i * 256 + tid;
        int row = c >> 2, ch = c & 3;
        long roff = (long)(n0 + row) * DV_ + k0 + ch * 8;
        uint32_t dd = row * B_ROWB + ch * 16;
        CP_ASYNC16(sbase + A_TB + dd, Bh + roff);
        CP_ASYNC16(sbase + A_TB + B_TB + dd, Bl + roff);
    }
}

__global__ void __launch_bounds__(256, 2) vr_gemm(
    const float* __restrict__ Af,
    const __nv_bfloat16* __restrict__ Bh, const __nv_bfloat16* __restrict__ Bl,
    const float* __restrict__ bias, float* __restrict__ C)
{
    extern __shared__ char smc[];
    uint32_t sb = smem_u32(smc);
    int tid = threadIdx.x, wid = tid >> 5, lane = tid & 31;
    int g = lane >> 2, tig = lane & 3;
    int wm = wid >> 2, wn = wid & 3;          // 2 x 4 warp grid
    int n0 = blockIdx.x * 128, m0 = blockIdx.y * 128;

    float acc[4][4][4];
#pragma unroll
    for (int a = 0; a < 4; a++)
#pragma unroll
        for (int b = 0; b < 4; b++)
#pragma unroll
            for (int cc = 0; cc < 4; cc++) acc[a][b][cc] = 0.f;

    // conversion-phase indices
    int crow = tid >> 1, ccol = (tid & 1) * 16;

    // ldmatrix per-thread base offsets
    uint32_t aRowOff = (uint32_t)(wm * 64 + (lane & 15)) * B_ROWB + (lane >> 4) * 16;
    uint32_t bRowOff = (uint32_t)(wn * 32 + (lane >> 4) * 8 + (lane & 7)) * B_ROWB
                       + ((lane >> 3) & 1) * 16;

    load_stage(sb, Af, Bh, Bl, m0, n0, 0, tid);
    CP_COMMIT();

    const int NKT = DV_ / BK;   // 128
    for (int kt = 0; kt < NKT; kt++) {
        if (kt + 1 < NKT) {
            load_stage(sb + ((kt + 1) & 1) * STAGE_B, Af, Bh, Bl,
                       m0, n0, (kt + 1) * BK, tid);
            CP_COMMIT();
            CP_WAIT(1);
        } else {
            CP_WAIT(0);
        }
        __syncthreads();   // stage ready; protects sAhi/sAlo from prev MMA phase

        const char* st = smc + (kt & 1) * STAGE_B;

        // ---- cooperative A split: fp32 tile -> sAhi / sAlo ----
        {
            const float* src = (const float*)st + crow * A_LDF + ccol;
            uint32_t hw[8], lw[8];
#pragma unroll
            for (int j = 0; j < 8; j++) {
                float2 v = *(const float2*)(src + 2 * j);
                splitpair(v, hw[j], lw[j]);
            }
            uint32_t* dh = (uint32_t*)(smc + AH_OFF) + crow * (B_LDT / 2) + (tid & 1) * 8;
            uint32_t* dl = (uint32_t*)(smc + AL_OFF) + crow * (B_LDT / 2) + (tid & 1) * 8;
            *(uint4*)dh       = make_uint4(hw[0], hw[1], hw[2], hw[3]);
            *(uint4*)(dh + 4) = make_uint4(hw[4], hw[5], hw[6], hw[7]);
            *(uint4*)dl       = make_uint4(lw[0], lw[1], lw[2], lw[3]);
            *(uint4*)(dl + 4) = make_uint4(lw[4], lw[5], lw[6], lw[7]);
        }
        __syncthreads();

        uint32_t aH = sb + AH_OFF + aRowOff;
        uint32_t aL = sb + AL_OFF + aRowOff;
        uint32_t bH = sb + (kt & 1) * STAGE_B + A_TB + bRowOff;
        uint32_t bL = bH + B_TB;

#pragma unroll
        for (int ks = 0; ks < 2; ks++) {
            uint32_t kso = ks * 32;           // 16 bf16 = 32B per k-chunk
            uint32_t bh[4][2], bl[4][2];
            ldsm_x4(bh[0][0], bh[0][1], bh[1][0], bh[1][1], bH + kso);
            ldsm_x4(bh[2][0], bh[2][1], bh[3][0], bh[3][1], bH + 16 * B_ROWB + kso);
            ldsm_x4(bl[0][0], bl[0][1], bl[1][0], bl[1][1], bL + kso);
            ldsm_x4(bl[2][0], bl[2][1], bl[3][0], bl[3][1], bL + 16 * B_ROWB + kso);
#pragma unroll
            for (int mi = 0; mi < 4; mi++) {
                uint32_t ah[4], al[4];
                ldsm_x4(ah[0], ah[1], ah[2], ah[3], aH + mi * 16 * B_ROWB + kso);
                ldsm_x4(al[0], al[1], al[2], al[3], aL + mi * 16 * B_ROWB + kso);
#pragma unroll
                for (int ni = 0; ni < 4; ni++) mma16816(acc[mi][ni], ah, bh[ni]);
#pragma unroll
                for (int ni = 0; ni < 4; ni++) mma16816(acc[mi][ni], ah, bl[ni]);
#pragma unroll
                for (int ni = 0; ni < 4; ni++) mma16816(acc[mi][ni], al, bh[ni]);
            }
        }
        __syncthreads();
    }

    // epilogue: C[m, n] = acc + bias[n]
#pragma unroll
    for (int mi = 0; mi < 4; mi++) {
        int mA = m0 + wm * 64 + mi * 16 + g;
#pragma unroll
        for (int ni = 0; ni < 4; ni++) {
            int n = n0 + wn * 32 + ni * 8 + tig * 2;
            float b0 = bias[n], b1 = bias[n + 1];
            float2 v0 = make_float2(acc[mi][ni][0] + b0, acc[mi][ni][1] + b1);
            float2 v1 = make_float2(acc[mi][ni][2] + b0, acc[mi][ni][3] + b1);
            *(float2*)&C[(long)mA * D_ + n] = v0;
            *(float2*)&C[(long)(mA + 8) * D_ + n] = v1;
        }
    }
}

// W [K=4096, N=1024] fp32 -> transposed split bf16 [N, K]
__global__ void splitW_kernel(const float* __restrict__ W,
                              __nv_bfloat16* __restrict__ hi, __nv_bfloat16* __restrict__ lo)
{
    __shared__ float t[32][33];
    int k0 = blockIdx.x * 32, n0 = blockIdx.y * 32;
    int tx = threadIdx.x, ty = threadIdx.y;
#pragma unroll
    for (int i = 0; i < 32; i += 8)
        t[ty + i][tx] = W[(long)(k0 + ty + i) * D_ + n0 + tx];
    __syncthreads();
#pragma unroll
    for (int i = 0; i < 32; i += 8) {
        int n = n0 + ty + i, k = k0 + tx;
        float x = t[tx][ty + i];
        __nv_bfloat16 h = __float2bfloat16(x);
        hi[(long)n * DV_ + k] = h;
        lo[(long)n * DV_ + k] = __float2bfloat16(x - __bfloat162float(h));
    }
}

// ---------------- fp32 SGEMM 64x64 tiles (Sr), register-pipelined ----------------
__global__ void sgemm64_bias(const float* __restrict__ A, const float* __restrict__ Bm,
                             const float* __restrict__ bias, float* __restrict__ C,
                             int M, int N, int K)
{
    const int BKs = 16;
    __shared__ float As[BKs][68];
    __shared__ float Bs[BKs][68];

    int tid = threadIdx.x;
    int m0 = blockIdx.y * 64, n0 = blockIdx.x * 64;
    int ty = tid >> 4, tx = tid & 15;

    float acc[4][4];
#pragma unroll
    for (int i = 0; i < 4; i++)
#pragma unroll
        for (int j = 0; j < 4; j++) acc[i][j] = 0.f;

    int arow = tid >> 2, acol = (tid & 3) * 4;
    int brow = tid >> 4, bcol = (tid & 15) * 4;

    // prologue: tile 0 in registers
    float4 ra = *(const float4*)&A[(long)(m0 + arow) * K + acol];
    float4 rb = *(const float4*)&Bm[(long)brow * N + n0 + bcol];

    for (int k0 = 0; k0 < K; k0 += BKs) {
        As[acol + 0][arow] = ra.x; As[acol + 1][arow] = ra.y;
        As[acol + 2][arow] = ra.z; As[acol + 3][arow] = ra.w;
        Bs[brow][bcol + 0] = rb.x; Bs[brow][bcol + 1] = rb.y;
        Bs[brow][bcol + 2] = rb.z; Bs[brow][bcol + 3] = rb.w;
        __syncthreads();

        if (k0 + BKs < K) {  // prefetch next tile while computing
            ra = *(const float4*)&A[(long)(m0 + arow) * K + k0 + BKs + acol];
            rb = *(const float4*)&Bm[(long)(k0 + BKs + brow) * N + n0 + bcol];
        }
#pragma unroll
        for (int kk = 0; kk < BKs; kk++) {
            float4 a = *(const float4*)&As[kk][ty * 4];
            float4 b = *(const float4*)&Bs[kk][tx * 4];
            float av[4] = {a.x, a.y, a.z, a.w};
            float bv[4] = {b.x, b.y, b.z, b.w};
#pragma unroll
            for (int i = 0; i < 4; i++)
#pragma unroll
                for (int j = 0; j < 4; j++) acc[i][j] += av[i] * bv[j];
        }
        __syncthreads();
    }

    float4 bb = *(const float4*)&bias[n0 + tx * 4];
    float bvv[4] = {bb.x, bb.y, bb.z, bb.w};
#pragma unroll
    for (int i = 0; i < 4; i++) {
        float4 o;
        o.x = acc[i][0] + bvv[0]; o.y = acc[i][1] + bvv[1];
        o.z = acc[i][2] + bvv[2]; o.w = acc[i][3] + bvv[3];
        *(float4*)&C[(long)(m0 + ty * 4 + i) * N + n0 + tx * 4] = o;
    }
}

// ---------------- Sr column norms ----------------
__global__ void snorm_kernel()
{
    int id = blockIdx.x * 256 + threadIdx.x;
    int b = id >> 10, d = id & 1023;
    float s = 0.f;
#pragma unroll
    for (int l = 0; l < L_; l++) {
        float v = g_Sr[(b * L_ + l) * D_ + d];
        s += v * v;
    }
    g_snorm[id] = sqrtf(s);
}

// ---------------- scores[b,l,t] = Sr[b,l,:]·Vr[b,t,:] ----------------
__global__ void scores_kernel()
{
    int b = blockIdx.y;
    int t0 = blockIdx.x * 64;
    __shared__ float sS[32][36];
    __shared__ float sV[32][68];
    int tid = threadIdx.x;
    int ty = tid >> 4, tx = tid & 15;
    float acc[2][4] = {{0, 0, 0, 0}, {0, 0, 0, 0}};

    int lrow = tid >> 3, kc = (tid & 7) * 4;
    for (int k0 = 0; k0 < D_; k0 += 32) {
        {
            float4 v = *(const float4*)&g_Sr[(b * L_ + lrow) * D_ + k0 + kc];
            sS[kc + 0][lrow] = v.x; sS[kc + 1][lrow] = v.y;
            sS[kc + 2][lrow] = v.z; sS[kc + 3][lrow] = v.w;
        }
#pragma unroll
        for (int i = 0; i < 2; i++) {
            int tt = lrow + i * 32;
            int t = t0 + tt;
            float4 w = make_float4(0.f, 0.f, 0.f, 0.f);
            if (t < T_) w = *(const float4*)&g_Vr[((long)b * T_ + t) * D_ + k0 + kc];
            sV[kc + 0][tt] = w.x; sV[kc + 1][tt] = w.y;
            sV[kc + 2][tt] = w.z; sV[kc + 3][tt] = w.w;
        }
        __syncthreads();
#pragma unroll
        for (int kk = 0; kk < 32; kk++) {
            float a0 = sS[kk][ty * 2], a1 = sS[kk][ty * 2 + 1];
            float4 bv = *(const float4*)&sV[kk][tx * 4];
            acc[0][0] += a0 * bv.x; acc[0][1] += a0 * bv.y;
            acc[0][2] += a0 * bv.z; acc[0][3] += a0 * bv.w;
            acc[1][0] += a1 * bv.x; acc[1][1] += a1 * bv.y;
            acc[1][2] += a1 * bv.z; acc[1][3] += a1 * bv.w;
        }
        __syncthreads();
    }
#pragma unroll
    for (int i = 0; i < 2; i++) {
        int l = ty * 2 + i;
#pragma unroll
        for (int j = 0; j < 4; j++) {
            int t = t0 + tx * 4 + j;
            if (t < T_) g_scores[(b * L_ + l) * T_ + t] = acc[i][j];
        }
    }
}

// ---------------- per-segment max/Z + exp weights ----------------
__global__ void segprep_kernel()
{
    int bl = blockIdx.x;
    __shared__ float sm[NSEG];
    int tid = threadIdx.x;
    const float* row = g_scores + bl * T_;
    if (tid < NSEG) {
        float mx = -INFINITY;
#pragma unroll
        for (int i = 0; i < FPS_; i++) mx = fmaxf(mx, row[tid * FPS_ + i]);
        float z = 0.f;
#pragma unroll
        for (int i = 0; i < FPS_; i++) z += expf(row[tid * FPS_ + i] - mx);
        sm[tid] = mx;
        g_m[bl * NSEG + tid] = mx;
        g_Zs[bl * NSEG + tid] = z;
    }
    __syncthreads();
    for (int t = tid; t < T_; t += 256)
        g_wtil[bl * T_ + t] = expf(row[t] - sm[t / FPS_]);
}

// ---------------- E[b,l,g,d] = sum_{t in seg g} wtil * Vr[b,t,d] ----------------
__global__ void eagg_kernel()
{
    int dc = blockIdx.x, g = blockIdx.y, b = blockIdx.z;
    int tid = threadIdx.x;
    int d = dc * 256 + tid;
    __shared__ float Vs[FPS_][256];
    __shared__ float ws[L_][FPS_ + 1];
#pragma unroll
    for (int t = 0; t < FPS_; t++)
        Vs[t][tid] = g_Vr[((long)b * T_ + g * FPS_ + t) * D_ + d];
    for (int i = tid; i < L_ * FPS_; i += 256) {
        int l = i / FPS_, t = i % FPS_;
        ws[l][t] = g_wtil[(b * L_ + l) * T_ + g * FPS_ + t];
    }
    __syncthreads();
    for (int l = 0; l < L_; l++) {
        float acc = 0.f;
#pragma unroll
        for (int t = 0; t < FPS_; t++) acc += ws[l][t] * Vs[t][tid];
        g_E[((long)(b * L_ + l) * NSEG + g) * D_ + d] = acc;
    }
}

// ============================================================================
// prop_kernel v3: barrier-free chain streaming.
// ============================================================================
#define PCH 128
__global__ void __launch_bounds__(PCH) prop_kernel(const int* __restrict__ ytrue,
                                                   float* __restrict__ outPos)
{
    int b = blockIdx.y, dc = blockIdx.x, sg = blockIdx.z;
    int tid = threadIdx.x;
    int d = dc * PCH + tid;

    __shared__ float s_m[L_][NSEG], s_Z[L_][NSEG];
    __shared__ float sSr[L_][PCH];
    __shared__ float c_sc[40][L_], c_an[40][L_], c_iz[40][L_];

    for (int i = tid; i < L_ * NSEG; i += PCH) {
        int l = i >> 4, g = i & 15;
        s_m[l][g] = g_m[(b * L_ + l) * NSEG + g];
        s_Z[l][g] = g_Zs[(b * L_ + l) * NSEG + g];
    }
    for (int i = tid; i < L_ * PCH; i += PCH) {
        int l = i / PCH, j = i % PCH;
        sSr[l][j] = g_Sr[(b * L_ + l) * D_ + dc * PCH + j];
    }
    __syncthreads();

    {
        int l = tid & 31, ci = tid >> 5;
        int s = sg + 4 * ci;
        int base = 0;
#pragma unroll
        for (int j = 0; j < 4; j++) if (j < ci) base += NSEG - (sg + 4 * j);
        float M = s_m[l][s], Zw = s_Z[l][s];
        c_sc[base][l] = 0.f; c_an[base][l] = 1.f; c_iz[base][l] = 1.f / Zw;
        for (int e = s + 1; e < NSEG; e++) {
            float mv = s_m[l][e];
            float Mn = fmaxf(M, mv);
            float sc = expf(M - Mn), an = expf(mv - Mn);
            Zw = Zw * sc + an * s_Z[l][e];
            M = Mn;
            int st = base + e - s;
            c_sc[st][l] = sc; c_an[st][l] = an; c_iz[st][l] = 1.f / Zw;
        }
    }
    __syncthreads();

    float sn = g_snorm[b * D_ + d];
    int ys = ytrue[2 * b], ye = ytrue[2 * b + 1];
    float negmax = -INFINITY;

    int base = 0;
#pragma unroll 1
    for (int ci = 0; ci < 4; ci++) {
        int s = sg + 4 * ci;
        float U[L_];
#pragma unroll
        for (int l = 0; l < L_; l++) U[l] = 0.f;
#pragma unroll 1
        for (int e = s; e < NSEG; e++) {
            int st = base + e - s;
            float num = 0.f, sq = 0.f;
            const float* Eb = g_E + ((long)(b * L_) * NSEG + e) * D_ + d;
#pragma unroll
            for (int l = 0; l < L_; l++) {
                float Ev = Eb[(long)l * NSEG * D_];
                float u = U[l] * c_sc[st][l] + c_an[st][l] * Ev;
                U[l] = u;
                float o = u * c_iz[st][l];
                num += o * sSr[l][tid];
                sq += o * o;
            }
            float scv = num / (sqrtf(sq) * sn + 1e-15f);
            if (s == ys && e == ye) outPos[b * D_ + d] = scv;
            else negmax = fmaxf(negmax, scv);
        }
        base += NSEG - s;
    }

#pragma unroll
    for (int off = 16; off; off >>= 1)
        negmax = fmaxf(negmax, __shfl_xor_sync(0xffffffffu, negmax, off));
    __shared__ float wm[4];
    if ((tid & 31) == 0) wm[tid >> 5] = negmax;
    __syncthreads();
    if (tid == 0) {
        float v = fmaxf(fmaxf(wm[0], wm[1]), fmaxf(wm[2], wm[3]));
        unsigned u = __float_as_uint(v);
        u = (u & 0x80000000u) ? ~u : (u | 0x80000000u);
        atomicMax(&g_negmax[b], u);
    }
}

__global__ void init_neg()
{
    if (threadIdx.x < B_) g_negmax[threadIdx.x] = 0x007FFFFFu;
}

__global__ void fin_kernel(float* __restrict__ outNeg)
{
    int b = threadIdx.x;
    if (b < B_) {
        unsigned u = g_negmax[b];
        unsigned bits = (u & 0x80000000u) ? (u ^ 0x80000000u) : ~u;
        outNeg[b] = __uint_as_float(bits);
    }
}

// ---------------- launch ----------------
extern "C" void kernel_launch(void* const* d_in, const int* in_sizes, int n_in,
                              void* d_out, int out_size)
{
    const float* videos    = (const float*)d_in[0];
    const float* sentences = (const float*)d_in[1];
    const float* Wv        = (const float*)d_in[2];
    const float* bv        = (const float*)d_in[3];
    const float* Ws        = (const float*)d_in[4];
    const float* bs        = (const float*)d_in[5];
    const int*   ytrue     = (const int*)d_in[6];
    float* out = (float*)d_out;

    float *pVr = nullptr, *pSr = nullptr;
    void *pBhi = nullptr, *pBlo = nullptr;
    cudaGetSymbolAddress((void**)&pVr, g_Vr);
    cudaGetSymbolAddress((void**)&pSr, g_Sr);
    cudaGetSymbolAddress(&pBhi, g_Bhi);
    cudaGetSymbolAddress(&pBlo, g_Blo);

    cudaFuncSetAttribute(vr_gemm, cudaFuncAttributeMaxDynamicSharedMemorySize, GEMM_SMEM);

    // side stream + events for the Sr path (created once; host-side only,
    // no device allocation, no graph nodes)
    static cudaStream_t s2 = nullptr;
    static cudaEvent_t evFork = nullptr, evJoin = nullptr;
    if (s2 == nullptr) {
        cudaStreamCreateWithFlags(&s2, cudaStreamNonBlocking);
        cudaEventCreateWithFlags(&evFork, cudaEventDisableTiming);
        cudaEventCreateWithFlags(&evJoin, cudaEventDisableTiming);
    }

    init_neg<<<1, 32>>>();

    // fork: Sr path (sgemm64 -> snorm) runs concurrently with Vr path
    cudaEventRecord(evFork, 0);
    cudaStreamWaitEvent(s2, evFork, 0);
    sgemm64_bias<<<dim3(D_ / 64, (B_ * L_) / 64), 256, 0, s2>>>(
        sentences, Ws, bs, pSr, B_ * L_, D_, DS_);
    snorm_kernel<<<(B_ * D_) / 256, 256, 0, s2>>>();
    cudaEventRecord(evJoin, s2);

    // Vr path on the main stream
    splitW_kernel<<<dim3(DV_ / 32, D_ / 32), dim3(32, 8)>>>(Wv,
        (__nv_bfloat16*)pBhi, (__nv_bfloat16*)pBlo);
    vr_gemm<<<dim3(D_ / 128, (B_ * T_) / 128), 256, GEMM_SMEM>>>(
        videos, (const __nv_bfloat16*)pBhi, (const __nv_bfloat16*)pBlo, bv, pVr);

    // join: everything below needs both Vr and Sr
    cudaStreamWaitEvent(0, evJoin, 0);

    scores_kernel<<<dim3((T_ + 63) / 64, B_), 256>>>();
    segprep_kernel<<<B_ * L_, 256>>>();
    eagg_kernel<<<dim3(D_ / 256, NSEG, B_), 256>>>();
    prop_kernel<<<dim3(D_ / PCH, B_, 4), PCH>>>(ytrue, out);
    fin_kernel<<<1, 32>>>(out + B_ * D_);
}